// round 12
// baseline (speedup 1.0000x reference)
#include <cuda_runtime.h>
#include <cuda_bf16.h>
#include <math.h>
#include <stdint.h>

// Problem constants
#define BATCH 2
#define SEQ   2048
#define DM    1024
#define NH    16
#define DH    64
#define DFF   512
#define ROWS  (BATCH*SEQ)          // 4096

// ---------------- scratch (device globals; no runtime allocation) ----------
__device__ float g_xn[ROWS*DM];    // norm1(x), tf32-rounded
__device__ float g_q [ROWS*DM];    // tf32 Q (pre-scaled by 1/8)
__device__ float g_k [ROWS*DM];    // tf32 K
__device__ float g_v [ROWS*DM];    // tf32 V
__device__ float g_kt[ROWS*DM];    // K transposed per head: [b*16+h][d][s]
__device__ float g_ao[ROWS*DM];    // attention output (tf32)
__device__ float g_x2[ROWS*DM];    // xn + attn@Wo + bo (fp32)
__device__ float g_hn[ROWS*DM];    // norm2(x2), tf32
__device__ float g_h1[ROWS*DFF];   // relu(hn@W1+b1), tf32
// tf32-converted weights
__device__ float g_wq[DM*DM];
__device__ float g_wk[DM*DM];
__device__ float g_wv[DM*DM];
__device__ float g_wo[DM*DM];
__device__ float g_w1[DM*DFF];
__device__ float g_w2[DFF*DM];

// ---------------- helpers ---------------------------------------------------
__device__ __forceinline__ float to_tf32(float x) {
    float r;
    asm("cvt.rna.tf32.f32 %0, %1;" : "=f"(r) : "f"(x));
    return r;
}

__device__ __forceinline__ void mma_tf32(float c[4],
                                         uint32_t a0, uint32_t a1, uint32_t a2, uint32_t a3,
                                         uint32_t b0, uint32_t b1) {
    asm volatile(
        "mma.sync.aligned.m16n8k8.row.col.f32.tf32.tf32.f32 "
        "{%0,%1,%2,%3}, {%4,%5,%6,%7}, {%8,%9}, {%0,%1,%2,%3};"
        : "+f"(c[0]), "+f"(c[1]), "+f"(c[2]), "+f"(c[3])
        : "r"(a0), "r"(a1), "r"(a2), "r"(a3), "r"(b0), "r"(b1));
}

__device__ __forceinline__ void cp_async16(uint32_t sdst, const void* gsrc) {
    asm volatile("cp.async.cg.shared.global [%0], [%1], 16;"
                 :: "r"(sdst), "l"(gsrc) : "memory");
}
__device__ __forceinline__ void cp_commit() {
    asm volatile("cp.async.commit_group;" ::: "memory");
}
__device__ __forceinline__ void cp_wait1() {
    asm volatile("cp.async.wait_group 1;" ::: "memory");
}
__device__ __forceinline__ void cp_wait0() {
    asm volatile("cp.async.wait_group 0;" ::: "memory");
}

// ---------------- fused weight tf32 pre-conversion (one launch) ------------
#define NQ4 (DM*DM/4)      // 262144 float4 per square weight
#define NF4 (DM*DFF/4)     // 131072 float4 per FFN weight
__global__ __launch_bounds__(256)
void wcvt_all(const float* __restrict__ Wq, const float* __restrict__ Wk,
              const float* __restrict__ Wv, const float* __restrict__ Wo,
              const float* __restrict__ W1, const float* __restrict__ W2,
              float* __restrict__ wq, float* __restrict__ wk,
              float* __restrict__ wv, float* __restrict__ wo,
              float* __restrict__ w1, float* __restrict__ w2)
{
    int i = blockIdx.x * 256 + threadIdx.x;
    const float* S; float* D; int off;
    if (i < 4 * NQ4) {
        int seg = i >> 18;           // /NQ4
        off = i & (NQ4 - 1);
        S = (seg == 0) ? Wq : (seg == 1) ? Wk : (seg == 2) ? Wv : Wo;
        D = (seg == 0) ? wq : (seg == 1) ? wk : (seg == 2) ? wv : wo;
    } else {
        int j = i - 4 * NQ4;
        if (j < NF4) { S = W1; D = w1; off = j; }
        else         { S = W2; D = w2; off = j - NF4; }
    }
    float4 v = ((const float4*)S)[off];
    v.x = to_tf32(v.x); v.y = to_tf32(v.y);
    v.z = to_tf32(v.z); v.w = to_tf32(v.w);
    ((float4*)D)[off] = v;
}

// ---------------- NormLayer (output optionally tf32-rounded) ---------------
template<bool CVT>
__global__ __launch_bounds__(256)
void norm_kernel(const float* __restrict__ X,
                 const float* __restrict__ alpha,
                 const float* __restrict__ beta,
                 float* __restrict__ Y)
{
    int row = blockIdx.x;
    int tid = threadIdx.x;
    const float* xr = X + (size_t)row * DM;

    float4 v = *(const float4*)(xr + tid * 4);
    float s  = v.x + v.y + v.z + v.w;
    float sq = v.x*v.x + v.y*v.y + v.z*v.z + v.w*v.w;

    #pragma unroll
    for (int m = 16; m; m >>= 1) {
        s  += __shfl_xor_sync(0xffffffffu, s,  m);
        sq += __shfl_xor_sync(0xffffffffu, sq, m);
    }
    __shared__ float red[16];
    __shared__ float s_mean, s_rstd;
    int wid  = tid >> 5;
    int lane = tid & 31;
    if (lane == 0) { red[wid] = s; red[8 + wid] = sq; }
    __syncthreads();
    if (tid == 0) {
        float S = 0.f, SQ = 0.f;
        #pragma unroll
        for (int w = 0; w < 8; w++) { S += red[w]; SQ += red[8 + w]; }
        float mean = S * (1.0f / DM);
        float var  = (SQ - (float)DM * mean * mean) * (1.0f / (DM - 1));
        s_mean = mean;
        s_rstd = rsqrtf(var + 1e-6f);
    }
    __syncthreads();
    float mean = s_mean, rstd = s_rstd;

    float4 a = *(const float4*)(alpha + tid * 4);
    float4 b = *(const float4*)(beta  + tid * 4);
    float4 o;
    o.x = a.x * (v.x - mean) * rstd + b.x;
    o.y = a.y * (v.y - mean) * rstd + b.y;
    o.z = a.z * (v.z - mean) * rstd + b.z;
    o.w = a.w * (v.w - mean) * rstd + b.w;
    if (CVT) {
        o.x = to_tf32(o.x); o.y = to_tf32(o.y);
        o.z = to_tf32(o.z); o.w = to_tf32(o.w);
    }
    *(float4*)(Y + (size_t)row * DM + tid * 4) = o;
}

// ---------------- per-head transpose: X[row][h*64+d] -> XT[bh][d][s] --------
__global__ __launch_bounds__(256)
void htrans_kernel(const float* __restrict__ X, float* __restrict__ XT)
{
    __shared__ float ts[64 * 65];
    int tid = threadIdx.x;
    int bh = blockIdx.y;
    int s0 = blockIdx.x * 64;
    size_t base = (size_t)(bh >> 4) * SEQ * DM + (bh & 15) * DH;

    for (int f = tid; f < 64 * 16; f += 256) {
        int s = f >> 4, c4 = (f & 15) << 2;
        float4 v = *(const float4*)(X + base + (size_t)(s0 + s) * DM + c4);
        ts[s * 65 + c4 + 0] = v.x;
        ts[s * 65 + c4 + 1] = v.y;
        ts[s * 65 + c4 + 2] = v.z;
        ts[s * 65 + c4 + 3] = v.w;
    }
    __syncthreads();
    for (int f = tid; f < 64 * 16; f += 256) {
        int d = f >> 4, s4 = (f & 15) << 2;
        float4 w;
        w.x = ts[(s4 + 0) * 65 + d];
        w.y = ts[(s4 + 1) * 65 + d];
        w.z = ts[(s4 + 2) * 65 + d];
        w.w = ts[(s4 + 3) * 65 + d];
        *(float4*)(XT + (size_t)(bh * DH + d) * SEQ + s0 + s4) = w;
    }
}

// ---------------- tgemm3: 128x128 block, 4 warps (64x64), cp.async ---------
#define GA_STR 20
#define GB_STR 136
#define G_SA0 0
#define G_SA1 (128 * GA_STR)
#define G_SB0 (2 * 128 * GA_STR)
#define G_SB1 (G_SB0 + 16 * GB_STR)
#define G_SMEM (G_SB0 + 2 * 16 * GB_STR)        // 9472 floats = 37888 B

template<bool RELU, bool HAS_RES, bool CVT_OUT>
__device__ __forceinline__ void gemm3_body(
    const float* __restrict__ A, const float* __restrict__ B,
    const float* __restrict__ bias, const float* __restrict__ Res,
    float* __restrict__ C, int N, int K, int bm, int bn, float outscale)
{
    __shared__ float sm[G_SMEM];
    uint32_t smb = (uint32_t)__cvta_generic_to_shared(sm);

    int tid  = threadIdx.x;
    int warp = tid >> 5, lane = tid & 31;
    int gid  = lane >> 2, tg = lane & 3;
    int wm   = (warp & 1) * 64;
    int wn   = (warp >> 1) * 64;

    int am[4], ac4[4], bk[4], bn4[4];
    #pragma unroll
    for (int i = 0; i < 4; i++) {
        int f = tid + 128 * i;
        am[i]  = f >> 2;
        ac4[i] = (f & 3) << 2;
        bk[i]  = f >> 5;
        bn4[i] = (f & 31) << 2;
    }
    const float* Ab = A + (size_t)(bm * 128) * K;
    const float* Bb = B + bn * 128;

    int nk = K >> 4;

    #pragma unroll
    for (int i = 0; i < 4; i++) {
        cp_async16(smb + (uint32_t)(G_SA0 + am[i] * GA_STR + ac4[i]) * 4,
                   Ab + (size_t)am[i] * K + ac4[i]);
        cp_async16(smb + (uint32_t)(G_SB0 + bk[i] * GB_STR + bn4[i]) * 4,
                   Bb + (size_t)bk[i] * N + bn4[i]);
    }
    cp_commit();

    float acc[4][8][4];
    #pragma unroll
    for (int mt = 0; mt < 4; mt++)
        #pragma unroll
        for (int nt = 0; nt < 8; nt++)
            #pragma unroll
            for (int r = 0; r < 4; r++) acc[mt][nt][r] = 0.f;

    for (int kt = 0; kt < nk; kt++) {
        int cur = kt & 1;
        if (kt + 1 < nk) {
            int k0 = (kt + 1) << 4;
            uint32_t sa = cur ? G_SA0 : G_SA1;
            uint32_t sb = cur ? G_SB0 : G_SB1;
            #pragma unroll
            for (int i = 0; i < 4; i++) {
                cp_async16(smb + (sa + am[i] * GA_STR + ac4[i]) * 4,
                           Ab + (size_t)am[i] * K + k0 + ac4[i]);
                cp_async16(smb + (sb + bk[i] * GB_STR + bn4[i]) * 4,
                           Bb + (size_t)(k0 + bk[i]) * N + bn4[i]);
            }
            cp_commit();
            cp_wait1();
        } else {
            cp_wait0();
        }
        __syncthreads();

        const float* As = sm + (cur ? G_SA1 : G_SA0);
        const float* Bs = sm + (cur ? G_SB1 : G_SB0);
        #pragma unroll
        for (int kk = 0; kk < 16; kk += 8) {
            uint32_t af[4][4], bf[8][2];
            #pragma unroll
            for (int mt = 0; mt < 4; mt++) {
                int r0 = (wm + mt * 16 + gid) * GA_STR;
                int r1 = (wm + mt * 16 + gid + 8) * GA_STR;
                af[mt][0] = __float_as_uint(As[r0 + kk + tg]);
                af[mt][1] = __float_as_uint(As[r1 + kk + tg]);
                af[mt][2] = __float_as_uint(As[r0 + kk + tg + 4]);
                af[mt][3] = __float_as_uint(As[r1 + kk + tg + 4]);
            }
            #pragma unroll
            for (int nt = 0; nt < 8; nt++) {
                int cc = wn + nt * 8 + gid;
                bf[nt][0] = __float_as_uint(Bs[(kk + tg) * GB_STR + cc]);
                bf[nt][1] = __float_as_uint(Bs[(kk + tg + 4) * GB_STR + cc]);
            }
            #pragma unroll
            for (int mt = 0; mt < 4; mt++)
                #pragma unroll
                for (int nt = 0; nt < 8; nt++)
                    mma_tf32(acc[mt][nt], af[mt][0], af[mt][1], af[mt][2], af[mt][3],
                             bf[nt][0], bf[nt][1]);
        }
        __syncthreads();
    }

    #pragma unroll
    for (int nt = 0; nt < 8; nt++) {
        int col = bn * 128 + wn + nt * 8 + 2 * tg;
        float2 bv = *(const float2*)(bias + col);
        #pragma unroll
        for (int mt = 0; mt < 4; mt++) {
            int r0 = bm * 128 + wm + mt * 16 + gid;
            int r1 = r0 + 8;
            float2 c0 = make_float2(acc[mt][nt][0] + bv.x, acc[mt][nt][1] + bv.y);
            float2 c1 = make_float2(acc[mt][nt][2] + bv.x, acc[mt][nt][3] + bv.y);
            if (RELU) {
                c0.x = fmaxf(c0.x, 0.f); c0.y = fmaxf(c0.y, 0.f);
                c1.x = fmaxf(c1.x, 0.f); c1.y = fmaxf(c1.y, 0.f);
            }
            if (HAS_RES) {
                float2 r0v = *(const float2*)(Res + (size_t)r0 * N + col);
                float2 r1v = *(const float2*)(Res + (size_t)r1 * N + col);
                c0.x += r0v.x; c0.y += r0v.y;
                c1.x += r1v.x; c1.y += r1v.y;
            }
            if (CVT_OUT) {
                c0.x = to_tf32(c0.x * outscale); c0.y = to_tf32(c0.y * outscale);
                c1.x = to_tf32(c1.x * outscale); c1.y = to_tf32(c1.y * outscale);
            }
            *(float2*)(C + (size_t)r0 * N + col) = c0;
            *(float2*)(C + (size_t)r1 * N + col) = c1;
        }
    }
}

template<bool RELU, bool HAS_RES, bool CVT_OUT>
__global__ __launch_bounds__(128)
void tgemm3(const float* __restrict__ A, const float* __restrict__ B,
            const float* __restrict__ bias, const float* __restrict__ Res,
            float* __restrict__ C, int N, int K)
{
    gemm3_body<RELU, HAS_RES, CVT_OUT>(A, B, bias, Res, C, N, K,
                                       blockIdx.y, blockIdx.x, 1.0f);
}

// fused QKV: blockIdx.x 0..23 -> sel = x>>3, col block = x&7.
__global__ __launch_bounds__(128)
void qkv_gemm3(const float* __restrict__ A,
               const float* __restrict__ Wq, const float* __restrict__ Wk,
               const float* __restrict__ Wv,
               const float* __restrict__ bq, const float* __restrict__ bk,
               const float* __restrict__ bv,
               float* __restrict__ Oq, float* __restrict__ Ok, float* __restrict__ Ov)
{
    int sel = blockIdx.x >> 3;
    int bn  = blockIdx.x & 7;
    const float* B    = (sel == 0) ? Wq : (sel == 1) ? Wk : Wv;
    const float* bias = (sel == 0) ? bq : (sel == 1) ? bk : bv;
    float* C          = (sel == 0) ? Oq : (sel == 1) ? Ok : Ov;
    float outscale    = (sel == 0) ? 0.125f : 1.0f;
    gemm3_body<false, false, true>(A, B, bias, nullptr, C, DM, DM,
                                   blockIdx.y, bn, outscale);
}

// ---------------- flash attention v4: K double-buffered, V single ----------
// 128 threads (4 warps), 64 queries/block, 64-key tiles.
// smem = 2x(KT 64x72) + 1x(V 64x72) = 55296 B -> 4 blocks/SM.
// Groups: ... [K(t), V(t)] -> wait1 gives K; commit K(t+1); S; softmax;
// wait1 (last: wait0) gives V; sync (also P-alias barrier); P into dead
// K buffer (XOR-4 swizzle); PV; sync; commit V(t+1).
#define KSTR 72
#define SM_K0 0
#define SM_K1 (64 * KSTR)
#define SM_V  (2 * 64 * KSTR)
#define ATT_SMEM_FLOATS (3 * 64 * KSTR)   // 13824 floats = 55296 B

__global__ __launch_bounds__(128, 4)
void attn4_kernel(const float* __restrict__ Q, const float* __restrict__ KT,
                  const float* __restrict__ Vb, float* __restrict__ O)
{
    extern __shared__ float sm[];
    uint32_t smb = (uint32_t)__cvta_generic_to_shared(sm);

    int tid  = threadIdx.x;
    int warp = tid >> 5, lane = tid & 31;
    int gid  = lane >> 2, tg = lane & 3;
    int wq   = warp * 16;
    int b4   = ((gid >> 2) & 1) << 2;   // P swizzle bit

    int bh = blockIdx.y;
    int q0 = blockIdx.x * 64;
    size_t base   = (size_t)(bh >> 4) * SEQ * DM + (bh & 15) * DH;
    size_t ktbase = (size_t)(bh * DH) * SEQ;

    int lr  = tid >> 4;            // 0..7
    int lc4 = (tid & 15) << 2;     // 0..60

    // ---- stage Q (tf32, pre-scaled) at stride 76, extract fragments
    for (int f = tid; f < 64 * 16; f += 128) {
        int qi = f >> 4, c4 = (f & 15) << 2;
        float4 v = *(const float4*)(Q + base + (size_t)(q0 + qi) * DM + c4);
        *(float4*)&sm[qi * 76 + c4] = v;
    }
    __syncthreads();

    uint32_t qf[8][4];
    #pragma unroll
    for (int ks = 0; ks < 8; ks++) {
        int k = ks * 8;
        int r0 = (wq + gid) * 76, r1 = (wq + gid + 8) * 76;
        qf[ks][0] = __float_as_uint(sm[r0 + k + tg]);
        qf[ks][1] = __float_as_uint(sm[r1 + k + tg]);
        qf[ks][2] = __float_as_uint(sm[r0 + k + tg + 4]);
        qf[ks][3] = __float_as_uint(sm[r1 + k + tg + 4]);
    }
    __syncthreads();

    float o[8][4];
    #pragma unroll
    for (int nt = 0; nt < 8; nt++)
        #pragma unroll
        for (int r = 0; r < 4; r++) o[nt][r] = 0.f;
    float m_lo = -INFINITY, m_hi = -INFINITY, l_lo = 0.f, l_hi = 0.f;

    const int NT = SEQ / 64;

    // ---- prologue: commit K0 group, then V0 group
    {
        uint32_t kdst = smb + SM_K0 * 4;
        const float* ksrc = KT + ktbase;
        #pragma unroll
        for (int i = 0; i < 8; i++) {
            int r = lr + i * 8;
            cp_async16(kdst + (uint32_t)(r * KSTR + lc4) * 4, ksrc + (size_t)r * SEQ + lc4);
        }
        cp_commit();
        uint32_t vdst = smb + SM_V * 4;
        const float* vsrc = Vb + base;
        #pragma unroll
        for (int i = 0; i < 8; i++) {
            int r = lr + i * 8;
            cp_async16(vdst + (uint32_t)(r * KSTR + lc4) * 4, vsrc + (size_t)r * DM + lc4);
        }
        cp_commit();
    }

    for (int kt = 0; kt < NT; kt++) {
        int cur = kt & 1;
        // K[t] ready (oldest pending group), V[t] may still be in flight
        cp_wait1();
        __syncthreads();

        // prefetch K[t+1] into the other K buffer
        if (kt + 1 < NT) {
            uint32_t kdst = smb + (cur ? SM_K0 : SM_K1) * 4;
            const float* ksrc = KT + ktbase + (kt + 1) * 64;
            #pragma unroll
            for (int i = 0; i < 8; i++) {
                int r = lr + i * 8;
                cp_async16(kdst + (uint32_t)(r * KSTR + lc4) * 4, ksrc + (size_t)r * SEQ + lc4);
            }
            cp_commit();
        }

        float* sKT = sm + (cur ? SM_K1 : SM_K0);
        const float* sV = sm + SM_V;

        // ---- S = Q @ K^T  (Q pre-scaled by 1/8)
        float s[8][4];
        #pragma unroll
        for (int nt = 0; nt < 8; nt++)
            #pragma unroll
            for (int r = 0; r < 4; r++) s[nt][r] = 0.f;

        #pragma unroll
        for (int ks = 0; ks < 8; ks++) {
            uint32_t bf[8][2];
            int kr0 = (ks * 8 + tg) * KSTR;
            int kr1 = (ks * 8 + tg + 4) * KSTR;
            #pragma unroll
            for (int nt = 0; nt < 8; nt++) {
                int cc = nt * 8 + gid;
                bf[nt][0] = __float_as_uint(sKT[kr0 + cc]);
                bf[nt][1] = __float_as_uint(sKT[kr1 + cc]);
            }
            #pragma unroll
            for (int nt = 0; nt < 8; nt++)
                mma_tf32(s[nt], qf[ks][0], qf[ks][1], qf[ks][2], qf[ks][3],
                         bf[nt][0], bf[nt][1]);
        }

        // ---- online softmax
        float mx_lo = -INFINITY, mx_hi = -INFINITY;
        #pragma unroll
        for (int nt = 0; nt < 8; nt++) {
            mx_lo = fmaxf(mx_lo, fmaxf(s[nt][0], s[nt][1]));
            mx_hi = fmaxf(mx_hi, fmaxf(s[nt][2], s[nt][3]));
        }
        #pragma unroll
        for (int off = 1; off < 4; off <<= 1) {
            mx_lo = fmaxf(mx_lo, __shfl_xor_sync(0xffffffffu, mx_lo, off));
            mx_hi = fmaxf(mx_hi, __shfl_xor_sync(0xffffffffu, mx_hi, off));
        }
        float mn_lo = fmaxf(m_lo, mx_lo);
        float mn_hi = fmaxf(m_hi, mx_hi);
        float al_lo = __expf(m_lo - mn_lo);
        float al_hi = __expf(m_hi - mn_hi);
        float ps_lo = 0.f, ps_hi = 0.f;
        #pragma unroll
        for (int nt = 0; nt < 8; nt++) {
            s[nt][0] = __expf(s[nt][0] - mn_lo);
            s[nt][1] = __expf(s[nt][1] - mn_lo);
            s[nt][2] = __expf(s[nt][2] - mn_hi);
            s[nt][3] = __expf(s[nt][3] - mn_hi);
            ps_lo += s[nt][0] + s[nt][1];
            ps_hi += s[nt][2] + s[nt][3];
        }
        #pragma unroll
        for (int off = 1; off < 4; off <<= 1) {
            ps_lo += __shfl_xor_sync(0xffffffffu, ps_lo, off);
            ps_hi += __shfl_xor_sync(0xffffffffu, ps_hi, off);
        }
        l_lo = l_lo * al_lo + ps_lo;
        l_hi = l_hi * al_hi + ps_hi;
        m_lo = mn_lo; m_hi = mn_hi;
        #pragma unroll
        for (int nt = 0; nt < 8; nt++) {
            o[nt][0] *= al_lo; o[nt][1] *= al_lo;
            o[nt][2] *= al_hi; o[nt][3] *= al_hi;
        }

        // ---- V[t] ready; barrier also closes S-reads of sKT[cur] (P alias)
        if (kt + 1 < NT) cp_wait1(); else cp_wait0();
        __syncthreads();

        // ---- write P (tf32) into dead K buffer, XOR-4 swizzle
        #pragma unroll
        for (int nt = 0; nt < 8; nt++) {
            int kc = nt * 8 + ((2 * tg) ^ b4);
            float2 p0 = make_float2(to_tf32(s[nt][0]), to_tf32(s[nt][1]));
            float2 p1 = make_float2(to_tf32(s[nt][2]), to_tf32(s[nt][3]));
            *(float2*)&sKT[(wq + gid) * KSTR + kc]     = p0;
            *(float2*)&sKT[(wq + gid + 8) * KSTR + kc] = p1;
        }
        __syncwarp();

        // ---- O += P @ V
        #pragma unroll
        for (int ks = 0; ks < 8; ks++) {
            uint32_t pa[4], bf[8][2];
            int r0 = (wq + gid) * KSTR, r1 = (wq + gid + 8) * KSTR;
            int klo = ks * 8 + (tg ^ b4);
            int khi = ks * 8 + ((tg + 4) ^ b4);
            pa[0] = __float_as_uint(sKT[r0 + klo]);
            pa[1] = __float_as_uint(sKT[r1 + klo]);
            pa[2] = __float_as_uint(sKT[r0 + khi]);
            pa[3] = __float_as_uint(sKT[r1 + khi]);
            int vr0 = (ks * 8 + tg) * KSTR;
            int vr1 = (ks * 8 + tg + 4) * KSTR;
            #pragma unroll
            for (int nt = 0; nt < 8; nt++) {
                int cc = nt * 8 + gid;
                bf[nt][0] = __float_as_uint(sV[vr0 + cc]);
                bf[nt][1] = __float_as_uint(sV[vr1 + cc]);
            }
            #pragma unroll
            for (int nt = 0; nt < 8; nt++)
                mma_tf32(o[nt], pa[0], pa[1], pa[2], pa[3], bf[nt][0], bf[nt][1]);
        }
        __syncthreads();   // all PV reads of V done

        // ---- now safe to overwrite V with V[t+1]
        if (kt + 1 < NT) {
            uint32_t vdst = smb + SM_V * 4;
            const float* vsrc = Vb + base + (size_t)((kt + 1) * 64) * DM;
            #pragma unroll
            for (int i = 0; i < 8; i++) {
                int r = lr + i * 8;
                cp_async16(vdst + (uint32_t)(r * KSTR + lc4) * 4, vsrc + (size_t)r * DM + lc4);
            }
            cp_commit();
        }
    }

    // ---- epilogue: normalize, tf32-round, store
    float inv_lo = 1.0f / l_lo;
    float inv_hi = 1.0f / l_hi;
    #pragma unroll
    for (int nt = 0; nt < 8; nt++) {
        int d = nt * 8 + 2 * tg;
        size_t r0 = base + (size_t)(q0 + wq + gid) * DM + d;
        size_t r1 = base + (size_t)(q0 + wq + gid + 8) * DM + d;
        *(float2*)(O + r0) = make_float2(to_tf32(o[nt][0] * inv_lo), to_tf32(o[nt][1] * inv_lo));
        *(float2*)(O + r1) = make_float2(to_tf32(o[nt][2] * inv_hi), to_tf32(o[nt][3] * inv_hi));
    }
}

// ---------------- launcher -------------------------------------------------
extern "C" void kernel_launch(void* const* d_in, const int* in_sizes, int n_in,
                              void* d_out, int out_size)
{
    const float* x      = (const float*)d_in[0];
    const float* Wq     = (const float*)d_in[1];
    const float* bq     = (const float*)d_in[2];
    const float* Wk     = (const float*)d_in[3];
    const float* bk     = (const float*)d_in[4];
    const float* Wv     = (const float*)d_in[5];
    const float* bv     = (const float*)d_in[6];
    const float* Wo     = (const float*)d_in[7];
    const float* bo     = (const float*)d_in[8];
    const float* alpha1 = (const float*)d_in[9];
    const float* beta1  = (const float*)d_in[10];
    const float* alpha2 = (const float*)d_in[11];
    const float* beta2  = (const float*)d_in[12];
    const float* W1     = (const float*)d_in[13];
    const float* b1     = (const float*)d_in[14];
    const float* W2     = (const float*)d_in[15];
    const float* b2     = (const float*)d_in[16];
    float* out = (float*)d_out;

    float *xn, *q, *k, *v, *kt, *ao, *x2, *hn, *h1;
    float *wq, *wk, *wv, *wo, *w1, *w2;
    cudaGetSymbolAddress((void**)&xn, g_xn);
    cudaGetSymbolAddress((void**)&q,  g_q);
    cudaGetSymbolAddress((void**)&k,  g_k);
    cudaGetSymbolAddress((void**)&v,  g_v);
    cudaGetSymbolAddress((void**)&kt, g_kt);
    cudaGetSymbolAddress((void**)&ao, g_ao);
    cudaGetSymbolAddress((void**)&x2, g_x2);
    cudaGetSymbolAddress((void**)&hn, g_hn);
    cudaGetSymbolAddress((void**)&h1, g_h1);
    cudaGetSymbolAddress((void**)&wq, g_wq);
    cudaGetSymbolAddress((void**)&wk, g_wk);
    cudaGetSymbolAddress((void**)&wv, g_wv);
    cudaGetSymbolAddress((void**)&wo, g_wo);
    cudaGetSymbolAddress((void**)&w1, g_w1);
    cudaGetSymbolAddress((void**)&w2, g_w2);

    // 0. fused weight tf32 pre-conversion (one launch)
    wcvt_all<<<(4 * NQ4 + 2 * NF4) / 256, 256>>>(Wq, Wk, Wv, Wo, W1, W2,
                                                 wq, wk, wv, wo, w1, w2);

    // 1. x_n = norm1(x), tf32
    norm_kernel<true><<<ROWS, 256>>>(x, alpha1, beta1, xn);

    // 2. fused Q/K/V projections (tf32 out; Q pre-scaled by 1/8)
    qkv_gemm3<<<dim3(24, ROWS / 128), 128>>>(xn, wq, wk, wv, bq, bk, bv, q, k, v);

    // 3. K per-head transpose
    htrans_kernel<<<dim3(SEQ / 64, BATCH * NH), 256>>>(k, kt);

    // 4. attention (4 blocks/SM)
    int att_smem = ATT_SMEM_FLOATS * (int)sizeof(float);   // 55296 B
    cudaFuncSetAttribute(attn4_kernel, cudaFuncAttributeMaxDynamicSharedMemorySize, att_smem);
    attn4_kernel<<<dim3(SEQ / 64, BATCH * NH), 128, att_smem>>>(q, kt, v, ao);

    // 5. x2 = x_n + ao@Wo + bo (fp32 out)
    tgemm3<false, true, false><<<dim3(DM / 128, ROWS / 128), 128>>>(ao, wo, bo, xn, x2, DM, DM);

    // 6. h_n = norm2(x2), tf32
    norm_kernel<true><<<ROWS, 256>>>(x2, alpha2, beta2, hn);

    // 7. h1 = relu(h_n@W1 + b1), tf32
    tgemm3<true, false, true><<<dim3(DFF / 128, ROWS / 128), 128>>>(hn, w1, b1, nullptr, h1, DFF, DM);

    // 8. out = x2 + h1@W2 + b2 (fp32)
    tgemm3<false, true, false><<<dim3(DM / 128, ROWS / 128), 128>>>(h1, w2, b2, x2, out, DM, DFF);
}

// round 13
// speedup vs baseline: 1.5377x; 1.5377x over previous
#include <cuda_runtime.h>
#include <cuda_bf16.h>
#include <math.h>
#include <stdint.h>

// Problem constants
#define BATCH 2
#define SEQ   2048
#define DM    1024
#define NH    16
#define DH    64
#define DFF   512
#define ROWS  (BATCH*SEQ)          // 4096

// ---------------- scratch (device globals; no runtime allocation) ----------
__device__ float g_xn[ROWS*DM];    // norm1(x), tf32-rounded
__device__ float g_q [ROWS*DM];    // tf32 Q (pre-scaled by 1/8)
__device__ float g_k [ROWS*DM];    // tf32 K
__device__ float g_v [ROWS*DM];    // tf32 V
__device__ float g_kt[ROWS*DM];    // K transposed per head: [b*16+h][d][s]
__device__ float g_ao[ROWS*DM];    // attention output (tf32)
__device__ float g_x2[ROWS*DM];    // xn + attn@Wo + bo (fp32)
__device__ float g_hn[ROWS*DM];    // norm2(x2), tf32
__device__ float g_h1[ROWS*DFF];   // relu(hn@W1+b1), tf32
// tf32-converted weights
__device__ float g_wq[DM*DM];
__device__ float g_wk[DM*DM];
__device__ float g_wv[DM*DM];
__device__ float g_wo[DM*DM];
__device__ float g_w1[DM*DFF];
__device__ float g_w2[DFF*DM];

// ---------------- helpers ---------------------------------------------------
__device__ __forceinline__ float to_tf32(float x) {
    float r;
    asm("cvt.rna.tf32.f32 %0, %1;" : "=f"(r) : "f"(x));
    return r;
}

__device__ __forceinline__ void mma_tf32(float c[4],
                                         uint32_t a0, uint32_t a1, uint32_t a2, uint32_t a3,
                                         uint32_t b0, uint32_t b1) {
    asm volatile(
        "mma.sync.aligned.m16n8k8.row.col.f32.tf32.tf32.f32 "
        "{%0,%1,%2,%3}, {%4,%5,%6,%7}, {%8,%9}, {%0,%1,%2,%3};"
        : "+f"(c[0]), "+f"(c[1]), "+f"(c[2]), "+f"(c[3])
        : "r"(a0), "r"(a1), "r"(a2), "r"(a3), "r"(b0), "r"(b1));
}

__device__ __forceinline__ void cp_async16(uint32_t sdst, const void* gsrc) {
    asm volatile("cp.async.cg.shared.global [%0], [%1], 16;"
                 :: "r"(sdst), "l"(gsrc) : "memory");
}
__device__ __forceinline__ void cp_commit() {
    asm volatile("cp.async.commit_group;" ::: "memory");
}
__device__ __forceinline__ void cp_wait1() {
    asm volatile("cp.async.wait_group 1;" ::: "memory");
}
__device__ __forceinline__ void cp_wait0() {
    asm volatile("cp.async.wait_group 0;" ::: "memory");
}

// ---------------- fused weight tf32 pre-conversion (one launch) ------------
#define NQ4 (DM*DM/4)      // 262144 float4 per square weight
#define NF4 (DM*DFF/4)     // 131072 float4 per FFN weight
__global__ __launch_bounds__(256)
void wcvt_all(const float* __restrict__ Wq, const float* __restrict__ Wk,
              const float* __restrict__ Wv, const float* __restrict__ Wo,
              const float* __restrict__ W1, const float* __restrict__ W2,
              float* __restrict__ wq, float* __restrict__ wk,
              float* __restrict__ wv, float* __restrict__ wo,
              float* __restrict__ w1, float* __restrict__ w2)
{
    int i = blockIdx.x * 256 + threadIdx.x;
    const float* S; float* D; int off;
    if (i < 4 * NQ4) {
        int seg = i >> 18;           // /NQ4
        off = i & (NQ4 - 1);
        S = (seg == 0) ? Wq : (seg == 1) ? Wk : (seg == 2) ? Wv : Wo;
        D = (seg == 0) ? wq : (seg == 1) ? wk : (seg == 2) ? wv : wo;
    } else {
        int j = i - 4 * NQ4;
        if (j < NF4) { S = W1; D = w1; off = j; }
        else         { S = W2; D = w2; off = j - NF4; }
    }
    float4 v = ((const float4*)S)[off];
    v.x = to_tf32(v.x); v.y = to_tf32(v.y);
    v.z = to_tf32(v.z); v.w = to_tf32(v.w);
    ((float4*)D)[off] = v;
}

// ---------------- NormLayer (output optionally tf32-rounded) ---------------
template<bool CVT>
__global__ __launch_bounds__(256)
void norm_kernel(const float* __restrict__ X,
                 const float* __restrict__ alpha,
                 const float* __restrict__ beta,
                 float* __restrict__ Y)
{
    int row = blockIdx.x;
    int tid = threadIdx.x;
    const float* xr = X + (size_t)row * DM;

    float4 v = *(const float4*)(xr + tid * 4);
    float s  = v.x + v.y + v.z + v.w;
    float sq = v.x*v.x + v.y*v.y + v.z*v.z + v.w*v.w;

    #pragma unroll
    for (int m = 16; m; m >>= 1) {
        s  += __shfl_xor_sync(0xffffffffu, s,  m);
        sq += __shfl_xor_sync(0xffffffffu, sq, m);
    }
    __shared__ float red[16];
    __shared__ float s_mean, s_rstd;
    int wid  = tid >> 5;
    int lane = tid & 31;
    if (lane == 0) { red[wid] = s; red[8 + wid] = sq; }
    __syncthreads();
    if (tid == 0) {
        float S = 0.f, SQ = 0.f;
        #pragma unroll
        for (int w = 0; w < 8; w++) { S += red[w]; SQ += red[8 + w]; }
        float mean = S * (1.0f / DM);
        float var  = (SQ - (float)DM * mean * mean) * (1.0f / (DM - 1));
        s_mean = mean;
        s_rstd = rsqrtf(var + 1e-6f);
    }
    __syncthreads();
    float mean = s_mean, rstd = s_rstd;

    float4 a = *(const float4*)(alpha + tid * 4);
    float4 b = *(const float4*)(beta  + tid * 4);
    float4 o;
    o.x = a.x * (v.x - mean) * rstd + b.x;
    o.y = a.y * (v.y - mean) * rstd + b.y;
    o.z = a.z * (v.z - mean) * rstd + b.z;
    o.w = a.w * (v.w - mean) * rstd + b.w;
    if (CVT) {
        o.x = to_tf32(o.x); o.y = to_tf32(o.y);
        o.z = to_tf32(o.z); o.w = to_tf32(o.w);
    }
    *(float4*)(Y + (size_t)row * DM + tid * 4) = o;
}

// ---------------- per-head transpose: X[row][h*64+d] -> XT[bh][d][s] --------
__global__ __launch_bounds__(256)
void htrans_kernel(const float* __restrict__ X, float* __restrict__ XT)
{
    __shared__ float ts[64 * 65];
    int tid = threadIdx.x;
    int bh = blockIdx.y;
    int s0 = blockIdx.x * 64;
    size_t base = (size_t)(bh >> 4) * SEQ * DM + (bh & 15) * DH;

    for (int f = tid; f < 64 * 16; f += 256) {
        int s = f >> 4, c4 = (f & 15) << 2;
        float4 v = *(const float4*)(X + base + (size_t)(s0 + s) * DM + c4);
        ts[s * 65 + c4 + 0] = v.x;
        ts[s * 65 + c4 + 1] = v.y;
        ts[s * 65 + c4 + 2] = v.z;
        ts[s * 65 + c4 + 3] = v.w;
    }
    __syncthreads();
    for (int f = tid; f < 64 * 16; f += 256) {
        int d = f >> 4, s4 = (f & 15) << 2;
        float4 w;
        w.x = ts[(s4 + 0) * 65 + d];
        w.y = ts[(s4 + 1) * 65 + d];
        w.z = ts[(s4 + 2) * 65 + d];
        w.w = ts[(s4 + 3) * 65 + d];
        *(float4*)(XT + (size_t)(bh * DH + d) * SEQ + s0 + s4) = w;
    }
}

// ---------------- tgemm3: 128x128 block, 4 warps (64x64), cp.async ---------
#define GA_STR 20
#define GB_STR 136
#define G_SA0 0
#define G_SA1 (128 * GA_STR)
#define G_SB0 (2 * 128 * GA_STR)
#define G_SB1 (G_SB0 + 16 * GB_STR)
#define G_SMEM (G_SB0 + 2 * 16 * GB_STR)        // 9472 floats = 37888 B

template<bool RELU, bool HAS_RES, bool CVT_OUT>
__device__ __forceinline__ void gemm3_body(
    const float* __restrict__ A, const float* __restrict__ B,
    const float* __restrict__ bias, const float* __restrict__ Res,
    float* __restrict__ C, int N, int K, int bm, int bn, float outscale)
{
    __shared__ float sm[G_SMEM];
    uint32_t smb = (uint32_t)__cvta_generic_to_shared(sm);

    int tid  = threadIdx.x;
    int warp = tid >> 5, lane = tid & 31;
    int gid  = lane >> 2, tg = lane & 3;
    int wm   = (warp & 1) * 64;
    int wn   = (warp >> 1) * 64;

    int am[4], ac4[4], bk[4], bn4[4];
    #pragma unroll
    for (int i = 0; i < 4; i++) {
        int f = tid + 128 * i;
        am[i]  = f >> 2;
        ac4[i] = (f & 3) << 2;
        bk[i]  = f >> 5;
        bn4[i] = (f & 31) << 2;
    }
    const float* Ab = A + (size_t)(bm * 128) * K;
    const float* Bb = B + bn * 128;

    int nk = K >> 4;

    #pragma unroll
    for (int i = 0; i < 4; i++) {
        cp_async16(smb + (uint32_t)(G_SA0 + am[i] * GA_STR + ac4[i]) * 4,
                   Ab + (size_t)am[i] * K + ac4[i]);
        cp_async16(smb + (uint32_t)(G_SB0 + bk[i] * GB_STR + bn4[i]) * 4,
                   Bb + (size_t)bk[i] * N + bn4[i]);
    }
    cp_commit();

    float acc[4][8][4];
    #pragma unroll
    for (int mt = 0; mt < 4; mt++)
        #pragma unroll
        for (int nt = 0; nt < 8; nt++)
            #pragma unroll
            for (int r = 0; r < 4; r++) acc[mt][nt][r] = 0.f;

    for (int kt = 0; kt < nk; kt++) {
        int cur = kt & 1;
        if (kt + 1 < nk) {
            int k0 = (kt + 1) << 4;
            uint32_t sa = cur ? G_SA0 : G_SA1;
            uint32_t sb = cur ? G_SB0 : G_SB1;
            #pragma unroll
            for (int i = 0; i < 4; i++) {
                cp_async16(smb + (sa + am[i] * GA_STR + ac4[i]) * 4,
                           Ab + (size_t)am[i] * K + k0 + ac4[i]);
                cp_async16(smb + (sb + bk[i] * GB_STR + bn4[i]) * 4,
                           Bb + (size_t)(k0 + bk[i]) * N + bn4[i]);
            }
            cp_commit();
            cp_wait1();
        } else {
            cp_wait0();
        }
        __syncthreads();

        const float* As = sm + (cur ? G_SA1 : G_SA0);
        const float* Bs = sm + (cur ? G_SB1 : G_SB0);
        #pragma unroll
        for (int kk = 0; kk < 16; kk += 8) {
            uint32_t af[4][4], bf[8][2];
            #pragma unroll
            for (int mt = 0; mt < 4; mt++) {
                int r0 = (wm + mt * 16 + gid) * GA_STR;
                int r1 = (wm + mt * 16 + gid + 8) * GA_STR;
                af[mt][0] = __float_as_uint(As[r0 + kk + tg]);
                af[mt][1] = __float_as_uint(As[r1 + kk + tg]);
                af[mt][2] = __float_as_uint(As[r0 + kk + tg + 4]);
                af[mt][3] = __float_as_uint(As[r1 + kk + tg + 4]);
            }
            #pragma unroll
            for (int nt = 0; nt < 8; nt++) {
                int cc = wn + nt * 8 + gid;
                bf[nt][0] = __float_as_uint(Bs[(kk + tg) * GB_STR + cc]);
                bf[nt][1] = __float_as_uint(Bs[(kk + tg + 4) * GB_STR + cc]);
            }
            #pragma unroll
            for (int mt = 0; mt < 4; mt++)
                #pragma unroll
                for (int nt = 0; nt < 8; nt++)
                    mma_tf32(acc[mt][nt], af[mt][0], af[mt][1], af[mt][2], af[mt][3],
                             bf[nt][0], bf[nt][1]);
        }
        __syncthreads();
    }

    #pragma unroll
    for (int nt = 0; nt < 8; nt++) {
        int col = bn * 128 + wn + nt * 8 + 2 * tg;
        float2 bv = *(const float2*)(bias + col);
        #pragma unroll
        for (int mt = 0; mt < 4; mt++) {
            int r0 = bm * 128 + wm + mt * 16 + gid;
            int r1 = r0 + 8;
            float2 c0 = make_float2(acc[mt][nt][0] + bv.x, acc[mt][nt][1] + bv.y);
            float2 c1 = make_float2(acc[mt][nt][2] + bv.x, acc[mt][nt][3] + bv.y);
            if (RELU) {
                c0.x = fmaxf(c0.x, 0.f); c0.y = fmaxf(c0.y, 0.f);
                c1.x = fmaxf(c1.x, 0.f); c1.y = fmaxf(c1.y, 0.f);
            }
            if (HAS_RES) {
                float2 r0v = *(const float2*)(Res + (size_t)r0 * N + col);
                float2 r1v = *(const float2*)(Res + (size_t)r1 * N + col);
                c0.x += r0v.x; c0.y += r0v.y;
                c1.x += r1v.x; c1.y += r1v.y;
            }
            if (CVT_OUT) {
                c0.x = to_tf32(c0.x * outscale); c0.y = to_tf32(c0.y * outscale);
                c1.x = to_tf32(c1.x * outscale); c1.y = to_tf32(c1.y * outscale);
            }
            *(float2*)(C + (size_t)r0 * N + col) = c0;
            *(float2*)(C + (size_t)r1 * N + col) = c1;
        }
    }
}

template<bool RELU, bool HAS_RES, bool CVT_OUT>
__global__ __launch_bounds__(128)
void tgemm3(const float* __restrict__ A, const float* __restrict__ B,
            const float* __restrict__ bias, const float* __restrict__ Res,
            float* __restrict__ C, int N, int K)
{
    gemm3_body<RELU, HAS_RES, CVT_OUT>(A, B, bias, Res, C, N, K,
                                       blockIdx.y, blockIdx.x, 1.0f);
}

// fused QKV: blockIdx.x 0..23 -> sel = x>>3, col block = x&7.
__global__ __launch_bounds__(128)
void qkv_gemm3(const float* __restrict__ A,
               const float* __restrict__ Wq, const float* __restrict__ Wk,
               const float* __restrict__ Wv,
               const float* __restrict__ bq, const float* __restrict__ bk,
               const float* __restrict__ bv,
               float* __restrict__ Oq, float* __restrict__ Ok, float* __restrict__ Ov)
{
    int sel = blockIdx.x >> 3;
    int bn  = blockIdx.x & 7;
    const float* B    = (sel == 0) ? Wq : (sel == 1) ? Wk : Wv;
    const float* bias = (sel == 0) ? bq : (sel == 1) ? bk : bv;
    float* C          = (sel == 0) ? Oq : (sel == 1) ? Ok : Ov;
    float outscale    = (sel == 0) ? 0.125f : 1.0f;
    gemm3_body<false, false, true>(A, B, bias, nullptr, C, DM, DM,
                                   blockIdx.y, bn, outscale);
}

// ---------------- flash attention: cp.async + P aliased into K buffer ------
// (R11 proven version: K AND V double-buffered, 73728 B, 3 blocks/SM)
#define KSTR 72
#define SM_KT0 0
#define SM_KT1 (64 * KSTR)
#define SM_V0  (2 * 64 * KSTR)
#define SM_V1  (3 * 64 * KSTR)
#define ATT_SMEM_FLOATS (4 * 64 * KSTR)   // 18432 floats = 73728 B

__global__ __launch_bounds__(128)
void attn3_kernel(const float* __restrict__ Q, const float* __restrict__ KT,
                  const float* __restrict__ Vb, float* __restrict__ O)
{
    extern __shared__ float sm[];
    uint32_t smb = (uint32_t)__cvta_generic_to_shared(sm);

    int tid  = threadIdx.x;
    int warp = tid >> 5, lane = tid & 31;
    int gid  = lane >> 2, tg = lane & 3;
    int wq   = warp * 16;
    int b4   = ((gid >> 2) & 1) << 2;   // P swizzle bit

    int bh = blockIdx.y;
    int q0 = blockIdx.x * 64;
    size_t base   = (size_t)(bh >> 4) * SEQ * DM + (bh & 15) * DH;
    size_t ktbase = (size_t)(bh * DH) * SEQ;

    int lr  = tid >> 4;            // 0..7
    int lc4 = (tid & 15) << 2;     // 0..60

    // ---- stage Q (tf32, pre-scaled) at stride 76 in KT region, extract frags
    for (int f = tid; f < 64 * 16; f += 128) {
        int q = f >> 4, c4 = (f & 15) << 2;
        float4 v = *(const float4*)(Q + base + (size_t)(q0 + q) * DM + c4);
        *(float4*)&sm[q * 76 + c4] = v;
    }
    __syncthreads();

    uint32_t qf[8][4];
    #pragma unroll
    for (int ks = 0; ks < 8; ks++) {
        int k = ks * 8;
        int r0 = (wq + gid) * 76, r1 = (wq + gid + 8) * 76;
        qf[ks][0] = __float_as_uint(sm[r0 + k + tg]);
        qf[ks][1] = __float_as_uint(sm[r1 + k + tg]);
        qf[ks][2] = __float_as_uint(sm[r0 + k + tg + 4]);
        qf[ks][3] = __float_as_uint(sm[r1 + k + tg + 4]);
    }
    __syncthreads();

    float o[8][4];
    #pragma unroll
    for (int nt = 0; nt < 8; nt++)
        #pragma unroll
        for (int r = 0; r < 4; r++) o[nt][r] = 0.f;
    float m_lo = -INFINITY, m_hi = -INFINITY, l_lo = 0.f, l_hi = 0.f;

    const int NT = SEQ / 64;

    // ---- prologue: async-load tile 0 into buffer 0
    {
        uint32_t kdst = smb + SM_KT0 * 4;
        uint32_t vdst = smb + SM_V0 * 4;
        const float* ksrc = KT + ktbase;
        const float* vsrc = Vb + base;
        #pragma unroll
        for (int i = 0; i < 8; i++) {
            int r = lr + i * 8;
            cp_async16(kdst + (uint32_t)(r * KSTR + lc4) * 4, ksrc + (size_t)r * SEQ + lc4);
            cp_async16(vdst + (uint32_t)(r * KSTR + lc4) * 4, vsrc + (size_t)r * DM + lc4);
        }
        cp_commit();
    }

    for (int kt = 0; kt < NT; kt++) {
        int cur = kt & 1;
        if (kt + 1 < NT) {
            int k0n = (kt + 1) * 64;
            uint32_t kdst = smb + (cur ? SM_KT0 : SM_KT1) * 4;
            uint32_t vdst = smb + (cur ? SM_V0 : SM_V1) * 4;
            const float* ksrc = KT + ktbase + k0n;
            const float* vsrc = Vb + base + (size_t)k0n * DM;
            #pragma unroll
            for (int i = 0; i < 8; i++) {
                int r = lr + i * 8;
                cp_async16(kdst + (uint32_t)(r * KSTR + lc4) * 4, ksrc + (size_t)r * SEQ + lc4);
                cp_async16(vdst + (uint32_t)(r * KSTR + lc4) * 4, vsrc + (size_t)r * DM + lc4);
            }
            cp_commit();
            cp_wait1();
        } else {
            cp_wait0();
        }
        __syncthreads();

        float* sKT = sm + (cur ? SM_KT1 : SM_KT0);
        const float* sV = sm + (cur ? SM_V1 : SM_V0);

        // ---- S = Q @ K^T  (Q pre-scaled by 1/8)
        float s[8][4];
        #pragma unroll
        for (int nt = 0; nt < 8; nt++)
            #pragma unroll
            for (int r = 0; r < 4; r++) s[nt][r] = 0.f;

        #pragma unroll
        for (int ks = 0; ks < 8; ks++) {
            uint32_t bf[8][2];
            int kr0 = (ks * 8 + tg) * KSTR;
            int kr1 = (ks * 8 + tg + 4) * KSTR;
            #pragma unroll
            for (int nt = 0; nt < 8; nt++) {
                int cc = nt * 8 + gid;
                bf[nt][0] = __float_as_uint(sKT[kr0 + cc]);
                bf[nt][1] = __float_as_uint(sKT[kr1 + cc]);
            }
            #pragma unroll
            for (int nt = 0; nt < 8; nt++)
                mma_tf32(s[nt], qf[ks][0], qf[ks][1], qf[ks][2], qf[ks][3],
                         bf[nt][0], bf[nt][1]);
        }

        // ---- online softmax
        float mx_lo = -INFINITY, mx_hi = -INFINITY;
        #pragma unroll
        for (int nt = 0; nt < 8; nt++) {
            mx_lo = fmaxf(mx_lo, fmaxf(s[nt][0], s[nt][1]));
            mx_hi = fmaxf(mx_hi, fmaxf(s[nt][2], s[nt][3]));
        }
        #pragma unroll
        for (int off = 1; off < 4; off <<= 1) {
            mx_lo = fmaxf(mx_lo, __shfl_xor_sync(0xffffffffu, mx_lo, off));
            mx_hi = fmaxf(mx_hi, __shfl_xor_sync(0xffffffffu, mx_hi, off));
        }
        float mn_lo = fmaxf(m_lo, mx_lo);
        float mn_hi = fmaxf(m_hi, mx_hi);
        float al_lo = __expf(m_lo - mn_lo);
        float al_hi = __expf(m_hi - mn_hi);
        float ps_lo = 0.f, ps_hi = 0.f;
        #pragma unroll
        for (int nt = 0; nt < 8; nt++) {
            s[nt][0] = __expf(s[nt][0] - mn_lo);
            s[nt][1] = __expf(s[nt][1] - mn_lo);
            s[nt][2] = __expf(s[nt][2] - mn_hi);
            s[nt][3] = __expf(s[nt][3] - mn_hi);
            ps_lo += s[nt][0] + s[nt][1];
            ps_hi += s[nt][2] + s[nt][3];
        }
        #pragma unroll
        for (int off = 1; off < 4; off <<= 1) {
            ps_lo += __shfl_xor_sync(0xffffffffu, ps_lo, off);
            ps_hi += __shfl_xor_sync(0xffffffffu, ps_hi, off);
        }
        l_lo = l_lo * al_lo + ps_lo;
        l_hi = l_hi * al_hi + ps_hi;
        m_lo = mn_lo; m_hi = mn_hi;
        #pragma unroll
        for (int nt = 0; nt < 8; nt++) {
            o[nt][0] *= al_lo; o[nt][1] *= al_lo;
            o[nt][2] *= al_hi; o[nt][3] *= al_hi;
        }

        // ---- all warps done reading sKT[cur]; reuse it for P
        __syncthreads();

        #pragma unroll
        for (int nt = 0; nt < 8; nt++) {
            int kc = nt * 8 + ((2 * tg) ^ b4);
            float2 p0 = make_float2(to_tf32(s[nt][0]), to_tf32(s[nt][1]));
            float2 p1 = make_float2(to_tf32(s[nt][2]), to_tf32(s[nt][3]));
            *(float2*)&sKT[(wq + gid) * KSTR + kc]     = p0;
            *(float2*)&sKT[(wq + gid + 8) * KSTR + kc] = p1;
        }
        __syncwarp();

        // ---- O += P @ V
        #pragma unroll
        for (int ks = 0; ks < 8; ks++) {
            uint32_t pa[4], bf[8][2];
            int r0 = (wq + gid) * KSTR, r1 = (wq + gid + 8) * KSTR;
            int klo = ks * 8 + (tg ^ b4);
            int khi = ks * 8 + ((tg + 4) ^ b4);
            pa[0] = __float_as_uint(sKT[r0 + klo]);
            pa[1] = __float_as_uint(sKT[r1 + klo]);
            pa[2] = __float_as_uint(sKT[r0 + khi]);
            pa[3] = __float_as_uint(sKT[r1 + khi]);
            int vr0 = (ks * 8 + tg) * KSTR;
            int vr1 = (ks * 8 + tg + 4) * KSTR;
            #pragma unroll
            for (int nt = 0; nt < 8; nt++) {
                int cc = nt * 8 + gid;
                bf[nt][0] = __float_as_uint(sV[vr0 + cc]);
                bf[nt][1] = __float_as_uint(sV[vr1 + cc]);
            }
            #pragma unroll
            for (int nt = 0; nt < 8; nt++)
                mma_tf32(o[nt], pa[0], pa[1], pa[2], pa[3], bf[nt][0], bf[nt][1]);
        }
        __syncthreads();   // compute done before next iter's cp.async overwrites
    }

    // ---- epilogue: normalize, tf32-round, store
    float inv_lo = 1.0f / l_lo;
    float inv_hi = 1.0f / l_hi;
    #pragma unroll
    for (int nt = 0; nt < 8; nt++) {
        int d = nt * 8 + 2 * tg;
        size_t r0 = base + (size_t)(q0 + wq + gid) * DM + d;
        size_t r1 = base + (size_t)(q0 + wq + gid + 8) * DM + d;
        *(float2*)(O + r0) = make_float2(to_tf32(o[nt][0] * inv_lo), to_tf32(o[nt][1] * inv_lo));
        *(float2*)(O + r1) = make_float2(to_tf32(o[nt][2] * inv_hi), to_tf32(o[nt][3] * inv_hi));
    }
}

// ---------------- launcher -------------------------------------------------
extern "C" void kernel_launch(void* const* d_in, const int* in_sizes, int n_in,
                              void* d_out, int out_size)
{
    const float* x      = (const float*)d_in[0];
    const float* Wq     = (const float*)d_in[1];
    const float* bq     = (const float*)d_in[2];
    const float* Wk     = (const float*)d_in[3];
    const float* bk     = (const float*)d_in[4];
    const float* Wv     = (const float*)d_in[5];
    const float* bv     = (const float*)d_in[6];
    const float* Wo     = (const float*)d_in[7];
    const float* bo     = (const float*)d_in[8];
    const float* alpha1 = (const float*)d_in[9];
    const float* beta1  = (const float*)d_in[10];
    const float* alpha2 = (const float*)d_in[11];
    const float* beta2  = (const float*)d_in[12];
    const float* W1     = (const float*)d_in[13];
    const float* b1     = (const float*)d_in[14];
    const float* W2     = (const float*)d_in[15];
    const float* b2     = (const float*)d_in[16];
    float* out = (float*)d_out;

    float *xn, *q, *k, *v, *kt, *ao, *x2, *hn, *h1;
    float *wq, *wk, *wv, *wo, *w1, *w2;
    cudaGetSymbolAddress((void**)&xn, g_xn);
    cudaGetSymbolAddress((void**)&q,  g_q);
    cudaGetSymbolAddress((void**)&k,  g_k);
    cudaGetSymbolAddress((void**)&v,  g_v);
    cudaGetSymbolAddress((void**)&kt, g_kt);
    cudaGetSymbolAddress((void**)&ao, g_ao);
    cudaGetSymbolAddress((void**)&x2, g_x2);
    cudaGetSymbolAddress((void**)&hn, g_hn);
    cudaGetSymbolAddress((void**)&h1, g_h1);
    cudaGetSymbolAddress((void**)&wq, g_wq);
    cudaGetSymbolAddress((void**)&wk, g_wk);
    cudaGetSymbolAddress((void**)&wv, g_wv);
    cudaGetSymbolAddress((void**)&wo, g_wo);
    cudaGetSymbolAddress((void**)&w1, g_w1);
    cudaGetSymbolAddress((void**)&w2, g_w2);

    // 0. fused weight tf32 pre-conversion (one launch)
    wcvt_all<<<(4 * NQ4 + 2 * NF4) / 256, 256>>>(Wq, Wk, Wv, Wo, W1, W2,
                                                 wq, wk, wv, wo, w1, w2);

    // 1. x_n = norm1(x), tf32
    norm_kernel<true><<<ROWS, 256>>>(x, alpha1, beta1, xn);

    // 2. fused Q/K/V projections (tf32 out; Q pre-scaled by 1/8)
    qkv_gemm3<<<dim3(24, ROWS / 128), 128>>>(xn, wq, wk, wv, bq, bk, bv, q, k, v);

    // 3. K per-head transpose
    htrans_kernel<<<dim3(SEQ / 64, BATCH * NH), 256>>>(k, kt);

    // 4. attention (3 blocks/SM, proven R11 version)
    int att_smem = ATT_SMEM_FLOATS * (int)sizeof(float);   // 73728 B
    cudaFuncSetAttribute(attn3_kernel, cudaFuncAttributeMaxDynamicSharedMemorySize, att_smem);
    attn3_kernel<<<dim3(SEQ / 64, BATCH * NH), 128, att_smem>>>(q, kt, v, ao);

    // 5. x2 = x_n + ao@Wo + bo (fp32 out)
    tgemm3<false, true, false><<<dim3(DM / 128, ROWS / 128), 128>>>(ao, wo, bo, xn, x2, DM, DM);

    // 6. h_n = norm2(x2), tf32
    norm_kernel<true><<<ROWS, 256>>>(x2, alpha2, beta2, hn);

    // 7. h1 = relu(h_n@W1 + b1), tf32
    tgemm3<true, false, true><<<dim3(DFF / 128, ROWS / 128), 128>>>(hn, w1, b1, nullptr, h1, DFF, DM);

    // 8. out = x2 + h1@W2 + b2 (fp32)
    tgemm3<false, true, false><<<dim3(DM / 128, ROWS / 128), 128>>>(h1, w2, b2, x2, out, DM, DFF);
}

// round 14
// speedup vs baseline: 2.0996x; 1.3654x over previous
#include <cuda_runtime.h>
#include <cuda_fp16.h>
#include <math.h>
#include <stdint.h>

// Problem constants
#define BATCH 2
#define SEQ   2048
#define DM    1024
#define NH    16
#define DH    64
#define DFF   512
#define ROWS  (BATCH*SEQ)          // 4096

// ---------------- scratch (device globals; no runtime allocation) ----------
__device__ float g_xn[ROWS*DM];     // norm1(x), tf32-rounded (residual)
__device__ __half g_xnh[ROWS*DM];   // fp16 copy (QKV A)
__device__ float g_q [ROWS*DM];     // tf32 Q (pre-scaled by 1/8)
__device__ float g_k [ROWS*DM];     // tf32 K
__device__ float g_v [ROWS*DM];     // tf32 V
__device__ float g_kt[ROWS*DM];     // K transposed per head
__device__ __half g_aoh[ROWS*DM];   // attention output fp16 (Wo A)
__device__ float g_x2[ROWS*DM];     // xn + attn@Wo + bo (fp32)
__device__ __half g_hnh[ROWS*DM];   // norm2(x2) fp16 (FFN1 A)
__device__ __half g_h1h[ROWS*DFF];  // relu(hn@W1+b1) fp16 (FFN2 A)
// fp16-converted weights
__device__ __half g_wqh[DM*DM];
__device__ __half g_wkh[DM*DM];
__device__ __half g_wvh[DM*DM];
__device__ __half g_woh[DM*DM];
__device__ __half g_w1h[DM*DFF];
__device__ __half g_w2h[DFF*DM];

// ---------------- helpers ---------------------------------------------------
__device__ __forceinline__ float to_tf32(float x) {
    float r;
    asm("cvt.rna.tf32.f32 %0, %1;" : "=f"(r) : "f"(x));
    return r;
}

__device__ __forceinline__ void mma_tf32(float c[4],
                                         uint32_t a0, uint32_t a1, uint32_t a2, uint32_t a3,
                                         uint32_t b0, uint32_t b1) {
    asm volatile(
        "mma.sync.aligned.m16n8k8.row.col.f32.tf32.tf32.f32 "
        "{%0,%1,%2,%3}, {%4,%5,%6,%7}, {%8,%9}, {%0,%1,%2,%3};"
        : "+f"(c[0]), "+f"(c[1]), "+f"(c[2]), "+f"(c[3])
        : "r"(a0), "r"(a1), "r"(a2), "r"(a3), "r"(b0), "r"(b1));
}

__device__ __forceinline__ void mma_f16(float c[4],
                                        uint32_t a0, uint32_t a1, uint32_t a2, uint32_t a3,
                                        uint32_t b0, uint32_t b1) {
    asm volatile(
        "mma.sync.aligned.m16n8k16.row.col.f32.f16.f16.f32 "
        "{%0,%1,%2,%3}, {%4,%5,%6,%7}, {%8,%9}, {%0,%1,%2,%3};"
        : "+f"(c[0]), "+f"(c[1]), "+f"(c[2]), "+f"(c[3])
        : "r"(a0), "r"(a1), "r"(a2), "r"(a3), "r"(b0), "r"(b1));
}

__device__ __forceinline__ void ldsm_x4(uint32_t& r0, uint32_t& r1, uint32_t& r2, uint32_t& r3,
                                        uint32_t addr) {
    asm volatile("ldmatrix.sync.aligned.m8n8.x4.shared.b16 {%0,%1,%2,%3}, [%4];"
                 : "=r"(r0), "=r"(r1), "=r"(r2), "=r"(r3) : "r"(addr));
}
__device__ __forceinline__ void ldsm_x4_t(uint32_t& r0, uint32_t& r1, uint32_t& r2, uint32_t& r3,
                                          uint32_t addr) {
    asm volatile("ldmatrix.sync.aligned.m8n8.x4.trans.shared.b16 {%0,%1,%2,%3}, [%4];"
                 : "=r"(r0), "=r"(r1), "=r"(r2), "=r"(r3) : "r"(addr));
}

__device__ __forceinline__ void cp_async16(uint32_t sdst, const void* gsrc) {
    asm volatile("cp.async.cg.shared.global [%0], [%1], 16;"
                 :: "r"(sdst), "l"(gsrc) : "memory");
}
__device__ __forceinline__ void cp_commit() {
    asm volatile("cp.async.commit_group;" ::: "memory");
}
__device__ __forceinline__ void cp_wait1() {
    asm volatile("cp.async.wait_group 1;" ::: "memory");
}
__device__ __forceinline__ void cp_wait0() {
    asm volatile("cp.async.wait_group 0;" ::: "memory");
}

// ---------------- fused weight fp16 pre-conversion (one launch) ------------
#define NQ4 (DM*DM/4)
#define NF4 (DM*DFF/4)
__global__ __launch_bounds__(256)
void wcvt_all(const float* __restrict__ Wq, const float* __restrict__ Wk,
              const float* __restrict__ Wv, const float* __restrict__ Wo,
              const float* __restrict__ W1, const float* __restrict__ W2,
              __half* __restrict__ wq, __half* __restrict__ wk,
              __half* __restrict__ wv, __half* __restrict__ wo,
              __half* __restrict__ w1, __half* __restrict__ w2)
{
    int i = blockIdx.x * 256 + threadIdx.x;
    const float* S; __half* D; int off;
    if (i < 4 * NQ4) {
        int seg = i >> 18;
        off = i & (NQ4 - 1);
        S = (seg == 0) ? Wq : (seg == 1) ? Wk : (seg == 2) ? Wv : Wo;
        D = (seg == 0) ? wq : (seg == 1) ? wk : (seg == 2) ? wv : wo;
    } else {
        int j = i - 4 * NQ4;
        if (j < NF4) { S = W1; D = w1; off = j; }
        else         { S = W2; D = w2; off = j - NF4; }
    }
    float4 v = ((const float4*)S)[off];
    __half2 h01 = __floats2half2_rn(v.x, v.y);
    __half2 h23 = __floats2half2_rn(v.z, v.w);
    uint2 pk = make_uint2(*(uint32_t*)&h01, *(uint32_t*)&h23);
    ((uint2*)D)[off] = pk;
}

// ---------------- NormLayer: float (tf32) + fp16 dual output ---------------
__global__ __launch_bounds__(256)
void norm_kernel(const float* __restrict__ X,
                 const float* __restrict__ alpha,
                 const float* __restrict__ beta,
                 float* __restrict__ Y, __half* __restrict__ Yh)
{
    int row = blockIdx.x;
    int tid = threadIdx.x;
    const float* xr = X + (size_t)row * DM;

    float4 v = *(const float4*)(xr + tid * 4);
    float s  = v.x + v.y + v.z + v.w;
    float sq = v.x*v.x + v.y*v.y + v.z*v.z + v.w*v.w;

    #pragma unroll
    for (int m = 16; m; m >>= 1) {
        s  += __shfl_xor_sync(0xffffffffu, s,  m);
        sq += __shfl_xor_sync(0xffffffffu, sq, m);
    }
    __shared__ float red[16];
    __shared__ float s_mean, s_rstd;
    int wid  = tid >> 5;
    int lane = tid & 31;
    if (lane == 0) { red[wid] = s; red[8 + wid] = sq; }
    __syncthreads();
    if (tid == 0) {
        float S = 0.f, SQ = 0.f;
        #pragma unroll
        for (int w = 0; w < 8; w++) { S += red[w]; SQ += red[8 + w]; }
        float mean = S * (1.0f / DM);
        float var  = (SQ - (float)DM * mean * mean) * (1.0f / (DM - 1));
        s_mean = mean;
        s_rstd = rsqrtf(var + 1e-6f);
    }
    __syncthreads();
    float mean = s_mean, rstd = s_rstd;

    float4 a = *(const float4*)(alpha + tid * 4);
    float4 b = *(const float4*)(beta  + tid * 4);
    float4 o;
    o.x = a.x * (v.x - mean) * rstd + b.x;
    o.y = a.y * (v.y - mean) * rstd + b.y;
    o.z = a.z * (v.z - mean) * rstd + b.z;
    o.w = a.w * (v.w - mean) * rstd + b.w;
    // fp16 copy for GEMM A operand
    __half2 h01 = __floats2half2_rn(o.x, o.y);
    __half2 h23 = __floats2half2_rn(o.z, o.w);
    *(uint2*)(Yh + (size_t)row * DM + tid * 4) =
        make_uint2(*(uint32_t*)&h01, *(uint32_t*)&h23);
    // tf32-rounded float for residual path
    o.x = to_tf32(o.x); o.y = to_tf32(o.y);
    o.z = to_tf32(o.z); o.w = to_tf32(o.w);
    *(float4*)(Y + (size_t)row * DM + tid * 4) = o;
}

// ---------------- per-head transpose: X[row][h*64+d] -> XT[bh][d][s] --------
__global__ __launch_bounds__(256)
void htrans_kernel(const float* __restrict__ X, float* __restrict__ XT)
{
    __shared__ float ts[64 * 65];
    int tid = threadIdx.x;
    int bh = blockIdx.y;
    int s0 = blockIdx.x * 64;
    size_t base = (size_t)(bh >> 4) * SEQ * DM + (bh & 15) * DH;

    for (int f = tid; f < 64 * 16; f += 256) {
        int s = f >> 4, c4 = (f & 15) << 2;
        float4 v = *(const float4*)(X + base + (size_t)(s0 + s) * DM + c4);
        ts[s * 65 + c4 + 0] = v.x;
        ts[s * 65 + c4 + 1] = v.y;
        ts[s * 65 + c4 + 2] = v.z;
        ts[s * 65 + c4 + 3] = v.w;
    }
    __syncthreads();
    for (int f = tid; f < 64 * 16; f += 256) {
        int d = f >> 4, s4 = (f & 15) << 2;
        float4 w;
        w.x = ts[(s4 + 0) * 65 + d];
        w.y = ts[(s4 + 1) * 65 + d];
        w.z = ts[(s4 + 2) * 65 + d];
        w.w = ts[(s4 + 3) * 65 + d];
        *(float4*)(XT + (size_t)(bh * DH + d) * SEQ + s0 + s4) = w;
    }
}

// ---------------- tgemm4: fp16 m16n8k16 + ldmatrix, 128x128, 4 warps -------
// A [M,K] fp16 row-major, B [K,N] fp16 row-major. k-chunk 32, double-buffered.
// sA: 128 rows x 80 B (40 halves); sB: 32 rows x 272 B (136 halves).
#define F_SA0 0
#define F_SA1 10240
#define F_SB0 20480
#define F_SB1 29184
#define F_SMEM 37888

// OUT_MODE: 0 = fp32, 1 = tf32-rounded fp32 (x outscale), 2 = fp16
template<bool RELU, bool HAS_RES, int OUT_MODE>
__device__ __forceinline__ void gemm4_body(
    const __half* __restrict__ A, const __half* __restrict__ B,
    const float* __restrict__ bias, const float* __restrict__ Res,
    float* __restrict__ Cf, __half* __restrict__ Ch,
    int N, int K, int bm, int bn, float outscale)
{
    __shared__ __align__(16) char smc[F_SMEM];
    uint32_t smb = (uint32_t)__cvta_generic_to_shared(smc);

    int tid  = threadIdx.x;
    int warp = tid >> 5, lane = tid & 31;
    int gid  = lane >> 2, tg = lane & 3;
    int wm   = (warp & 1) * 64;
    int wn   = (warp >> 1) * 64;

    // ldmatrix lane addressing
    int a_row = (lane & 7) + ((lane >> 3) & 1) * 8;   // 0..15 within m16
    int a_k   = (lane >> 4) * 8;                      // 0 or 8 within k16
    int b_k   = a_row;                                // 0..15 within k16
    int b_n   = (lane >> 4) * 8;                      // 0 or 8 within n16

    // loader indices
    const __half* Ab = A + (size_t)(bm * 128) * K;
    const __half* Bb = B + bn * 128;
    int nk = K >> 5;   // chunks of 32

    // prologue: chunk 0 -> buf 0
    #pragma unroll
    for (int i = 0; i < 4; i++) {
        int f = tid + 128 * i;
        int ar = f >> 2, aj = f & 3;
        cp_async16(smb + F_SA0 + (uint32_t)(ar * 80 + aj * 16),
                   Ab + (size_t)ar * K + aj * 8);
        int br = f >> 4, bj = f & 15;
        cp_async16(smb + F_SB0 + (uint32_t)(br * 272 + bj * 16),
                   Bb + (size_t)br * N + bj * 8);
    }
    cp_commit();

    float acc[4][8][4];
    #pragma unroll
    for (int mt = 0; mt < 4; mt++)
        #pragma unroll
        for (int nt = 0; nt < 8; nt++)
            #pragma unroll
            for (int r = 0; r < 4; r++) acc[mt][nt][r] = 0.f;

    for (int kt = 0; kt < nk; kt++) {
        int cur = kt & 1;
        if (kt + 1 < nk) {
            int k0 = (kt + 1) << 5;
            uint32_t sa = cur ? F_SA0 : F_SA1;
            uint32_t sb = cur ? F_SB0 : F_SB1;
            #pragma unroll
            for (int i = 0; i < 4; i++) {
                int f = tid + 128 * i;
                int ar = f >> 2, aj = f & 3;
                cp_async16(smb + sa + (uint32_t)(ar * 80 + aj * 16),
                           Ab + (size_t)ar * K + k0 + aj * 8);
                int br = f >> 4, bj = f & 15;
                cp_async16(smb + sb + (uint32_t)(br * 272 + bj * 16),
                           Bb + (size_t)(k0 + br) * N + bj * 8);
            }
            cp_commit();
            cp_wait1();
        } else {
            cp_wait0();
        }
        __syncthreads();

        uint32_t aBase = smb + (cur ? F_SA1 : F_SA0);
        uint32_t bBase = smb + (cur ? F_SB1 : F_SB0);

        #pragma unroll
        for (int kk = 0; kk < 32; kk += 16) {
            uint32_t af[4][4], bf[8][2];
            #pragma unroll
            for (int mt = 0; mt < 4; mt++) {
                uint32_t addr = aBase + (uint32_t)((wm + mt * 16 + a_row) * 80
                                                   + (kk + a_k) * 2);
                ldsm_x4(af[mt][0], af[mt][1], af[mt][2], af[mt][3], addr);
            }
            #pragma unroll
            for (int nt2 = 0; nt2 < 4; nt2++) {
                uint32_t addr = bBase + (uint32_t)((kk + b_k) * 272
                                                   + (wn + nt2 * 16 + b_n) * 2);
                // trans x4: mats 0,1 -> n-tile 2*nt2 (b0,b1); mats 2,3 -> 2*nt2+1
                ldsm_x4_t(bf[nt2 * 2][0], bf[nt2 * 2][1],
                          bf[nt2 * 2 + 1][0], bf[nt2 * 2 + 1][1], addr);
            }
            #pragma unroll
            for (int mt = 0; mt < 4; mt++)
                #pragma unroll
                for (int nt = 0; nt < 8; nt++)
                    mma_f16(acc[mt][nt], af[mt][0], af[mt][1], af[mt][2], af[mt][3],
                            bf[nt][0], bf[nt][1]);
        }
        __syncthreads();
    }

    // epilogue
    #pragma unroll
    for (int nt = 0; nt < 8; nt++) {
        int col = bn * 128 + wn + nt * 8 + 2 * tg;
        float2 bv = *(const float2*)(bias + col);
        #pragma unroll
        for (int mt = 0; mt < 4; mt++) {
            int r0 = bm * 128 + wm + mt * 16 + gid;
            int r1 = r0 + 8;
            float2 c0 = make_float2(acc[mt][nt][0] + bv.x, acc[mt][nt][1] + bv.y);
            float2 c1 = make_float2(acc[mt][nt][2] + bv.x, acc[mt][nt][3] + bv.y);
            if (RELU) {
                c0.x = fmaxf(c0.x, 0.f); c0.y = fmaxf(c0.y, 0.f);
                c1.x = fmaxf(c1.x, 0.f); c1.y = fmaxf(c1.y, 0.f);
            }
            if (HAS_RES) {
                float2 r0v = *(const float2*)(Res + (size_t)r0 * N + col);
                float2 r1v = *(const float2*)(Res + (size_t)r1 * N + col);
                c0.x += r0v.x; c0.y += r0v.y;
                c1.x += r1v.x; c1.y += r1v.y;
            }
            if (OUT_MODE == 2) {
                __half2 h0 = __floats2half2_rn(c0.x, c0.y);
                __half2 h1 = __floats2half2_rn(c1.x, c1.y);
                *(uint32_t*)(Ch + (size_t)r0 * N + col) = *(uint32_t*)&h0;
                *(uint32_t*)(Ch + (size_t)r1 * N + col) = *(uint32_t*)&h1;
            } else {
                if (OUT_MODE == 1) {
                    c0.x = to_tf32(c0.x * outscale); c0.y = to_tf32(c0.y * outscale);
                    c1.x = to_tf32(c1.x * outscale); c1.y = to_tf32(c1.y * outscale);
                }
                *(float2*)(Cf + (size_t)r0 * N + col) = c0;
                *(float2*)(Cf + (size_t)r1 * N + col) = c1;
            }
        }
    }
}

template<bool RELU, bool HAS_RES, int OUT_MODE>
__global__ __launch_bounds__(128)
void tgemm4(const __half* __restrict__ A, const __half* __restrict__ B,
            const float* __restrict__ bias, const float* __restrict__ Res,
            float* __restrict__ Cf, __half* __restrict__ Ch, int N, int K)
{
    gemm4_body<RELU, HAS_RES, OUT_MODE>(A, B, bias, Res, Cf, Ch, N, K,
                                        blockIdx.y, blockIdx.x, 1.0f);
}

// fused QKV: blockIdx.x 0..23 -> sel = x>>3, col block = x&7. Float tf32 out.
__global__ __launch_bounds__(128)
void qkv_gemm4(const __half* __restrict__ A,
               const __half* __restrict__ Wq, const __half* __restrict__ Wk,
               const __half* __restrict__ Wv,
               const float* __restrict__ bq, const float* __restrict__ bk,
               const float* __restrict__ bv,
               float* __restrict__ Oq, float* __restrict__ Ok, float* __restrict__ Ov)
{
    int sel = blockIdx.x >> 3;
    int bn  = blockIdx.x & 7;
    const __half* B   = (sel == 0) ? Wq : (sel == 1) ? Wk : Wv;
    const float* bias = (sel == 0) ? bq : (sel == 1) ? bk : bv;
    float* C          = (sel == 0) ? Oq : (sel == 1) ? Ok : Ov;
    float outscale    = (sel == 0) ? 0.125f : 1.0f;
    gemm4_body<false, false, 1>(A, B, bias, nullptr, C, nullptr, DM, DM,
                                blockIdx.y, bn, outscale);
}

// ---------------- flash attention (R11/R13 proven tf32 version) ------------
#define KSTR 72
#define SM_KT0 0
#define SM_KT1 (64 * KSTR)
#define SM_V0  (2 * 64 * KSTR)
#define SM_V1  (3 * 64 * KSTR)
#define ATT_SMEM_FLOATS (4 * 64 * KSTR)   // 73728 B

__global__ __launch_bounds__(128)
void attn3_kernel(const float* __restrict__ Q, const float* __restrict__ KT,
                  const float* __restrict__ Vb, __half* __restrict__ Oh)
{
    extern __shared__ float sm[];
    uint32_t smb = (uint32_t)__cvta_generic_to_shared(sm);

    int tid  = threadIdx.x;
    int warp = tid >> 5, lane = tid & 31;
    int gid  = lane >> 2, tg = lane & 3;
    int wq   = warp * 16;
    int b4   = ((gid >> 2) & 1) << 2;

    int bh = blockIdx.y;
    int q0 = blockIdx.x * 64;
    size_t base   = (size_t)(bh >> 4) * SEQ * DM + (bh & 15) * DH;
    size_t ktbase = (size_t)(bh * DH) * SEQ;

    int lr  = tid >> 4;
    int lc4 = (tid & 15) << 2;

    for (int f = tid; f < 64 * 16; f += 128) {
        int q = f >> 4, c4 = (f & 15) << 2;
        float4 v = *(const float4*)(Q + base + (size_t)(q0 + q) * DM + c4);
        *(float4*)&sm[q * 76 + c4] = v;
    }
    __syncthreads();

    uint32_t qf[8][4];
    #pragma unroll
    for (int ks = 0; ks < 8; ks++) {
        int k = ks * 8;
        int r0 = (wq + gid) * 76, r1 = (wq + gid + 8) * 76;
        qf[ks][0] = __float_as_uint(sm[r0 + k + tg]);
        qf[ks][1] = __float_as_uint(sm[r1 + k + tg]);
        qf[ks][2] = __float_as_uint(sm[r0 + k + tg + 4]);
        qf[ks][3] = __float_as_uint(sm[r1 + k + tg + 4]);
    }
    __syncthreads();

    float o[8][4];
    #pragma unroll
    for (int nt = 0; nt < 8; nt++)
        #pragma unroll
        for (int r = 0; r < 4; r++) o[nt][r] = 0.f;
    float m_lo = -INFINITY, m_hi = -INFINITY, l_lo = 0.f, l_hi = 0.f;

    const int NT = SEQ / 64;

    {
        uint32_t kdst = smb + SM_KT0 * 4;
        uint32_t vdst = smb + SM_V0 * 4;
        const float* ksrc = KT + ktbase;
        const float* vsrc = Vb + base;
        #pragma unroll
        for (int i = 0; i < 8; i++) {
            int r = lr + i * 8;
            cp_async16(kdst + (uint32_t)(r * KSTR + lc4) * 4, ksrc + (size_t)r * SEQ + lc4);
            cp_async16(vdst + (uint32_t)(r * KSTR + lc4) * 4, vsrc + (size_t)r * DM + lc4);
        }
        cp_commit();
    }

    for (int kt = 0; kt < NT; kt++) {
        int cur = kt & 1;
        if (kt + 1 < NT) {
            int k0n = (kt + 1) * 64;
            uint32_t kdst = smb + (cur ? SM_KT0 : SM_KT1) * 4;
            uint32_t vdst = smb + (cur ? SM_V0 : SM_V1) * 4;
            const float* ksrc = KT + ktbase + k0n;
            const float* vsrc = Vb + base + (size_t)k0n * DM;
            #pragma unroll
            for (int i = 0; i < 8; i++) {
                int r = lr + i * 8;
                cp_async16(kdst + (uint32_t)(r * KSTR + lc4) * 4, ksrc + (size_t)r * SEQ + lc4);
                cp_async16(vdst + (uint32_t)(r * KSTR + lc4) * 4, vsrc + (size_t)r * DM + lc4);
            }
            cp_commit();
            cp_wait1();
        } else {
            cp_wait0();
        }
        __syncthreads();

        float* sKT = sm + (cur ? SM_KT1 : SM_KT0);
        const float* sV = sm + (cur ? SM_V1 : SM_V0);

        float s[8][4];
        #pragma unroll
        for (int nt = 0; nt < 8; nt++)
            #pragma unroll
            for (int r = 0; r < 4; r++) s[nt][r] = 0.f;

        #pragma unroll
        for (int ks = 0; ks < 8; ks++) {
            uint32_t bf[8][2];
            int kr0 = (ks * 8 + tg) * KSTR;
            int kr1 = (ks * 8 + tg + 4) * KSTR;
            #pragma unroll
            for (int nt = 0; nt < 8; nt++) {
                int cc = nt * 8 + gid;
                bf[nt][0] = __float_as_uint(sKT[kr0 + cc]);
                bf[nt][1] = __float_as_uint(sKT[kr1 + cc]);
            }
            #pragma unroll
            for (int nt = 0; nt < 8; nt++)
                mma_tf32(s[nt], qf[ks][0], qf[ks][1], qf[ks][2], qf[ks][3],
                         bf[nt][0], bf[nt][1]);
        }

        float mx_lo = -INFINITY, mx_hi = -INFINITY;
        #pragma unroll
        for (int nt = 0; nt < 8; nt++) {
            mx_lo = fmaxf(mx_lo, fmaxf(s[nt][0], s[nt][1]));
            mx_hi = fmaxf(mx_hi, fmaxf(s[nt][2], s[nt][3]));
        }
        #pragma unroll
        for (int off = 1; off < 4; off <<= 1) {
            mx_lo = fmaxf(mx_lo, __shfl_xor_sync(0xffffffffu, mx_lo, off));
            mx_hi = fmaxf(mx_hi, __shfl_xor_sync(0xffffffffu, mx_hi, off));
        }
        float mn_lo = fmaxf(m_lo, mx_lo);
        float mn_hi = fmaxf(m_hi, mx_hi);
        float al_lo = __expf(m_lo - mn_lo);
        float al_hi = __expf(m_hi - mn_hi);
        float ps_lo = 0.f, ps_hi = 0.f;
        #pragma unroll
        for (int nt = 0; nt < 8; nt++) {
            s[nt][0] = __expf(s[nt][0] - mn_lo);
            s[nt][1] = __expf(s[nt][1] - mn_lo);
            s[nt][2] = __expf(s[nt][2] - mn_hi);
            s[nt][3] = __expf(s[nt][3] - mn_hi);
            ps_lo += s[nt][0] + s[nt][1];
            ps_hi += s[nt][2] + s[nt][3];
        }
        #pragma unroll
        for (int off = 1; off < 4; off <<= 1) {
            ps_lo += __shfl_xor_sync(0xffffffffu, ps_lo, off);
            ps_hi += __shfl_xor_sync(0xffffffffu, ps_hi, off);
        }
        l_lo = l_lo * al_lo + ps_lo;
        l_hi = l_hi * al_hi + ps_hi;
        m_lo = mn_lo; m_hi = mn_hi;
        #pragma unroll
        for (int nt = 0; nt < 8; nt++) {
            o[nt][0] *= al_lo; o[nt][1] *= al_lo;
            o[nt][2] *= al_hi; o[nt][3] *= al_hi;
        }

        __syncthreads();

        #pragma unroll
        for (int nt = 0; nt < 8; nt++) {
            int kc = nt * 8 + ((2 * tg) ^ b4);
            float2 p0 = make_float2(to_tf32(s[nt][0]), to_tf32(s[nt][1]));
            float2 p1 = make_float2(to_tf32(s[nt][2]), to_tf32(s[nt][3]));
            *(float2*)&sKT[(wq + gid) * KSTR + kc]     = p0;
            *(float2*)&sKT[(wq + gid + 8) * KSTR + kc] = p1;
        }
        __syncwarp();

        #pragma unroll
        for (int ks = 0; ks < 8; ks++) {
            uint32_t pa[4], bf[8][2];
            int r0 = (wq + gid) * KSTR, r1 = (wq + gid + 8) * KSTR;
            int klo = ks * 8 + (tg ^ b4);
            int khi = ks * 8 + ((tg + 4) ^ b4);
            pa[0] = __float_as_uint(sKT[r0 + klo]);
            pa[1] = __float_as_uint(sKT[r1 + klo]);
            pa[2] = __float_as_uint(sKT[r0 + khi]);
            pa[3] = __float_as_uint(sKT[r1 + khi]);
            int vr0 = (ks * 8 + tg) * KSTR;
            int vr1 = (ks * 8 + tg + 4) * KSTR;
            #pragma unroll
            for (int nt = 0; nt < 8; nt++) {
                int cc = nt * 8 + gid;
                bf[nt][0] = __float_as_uint(sV[vr0 + cc]);
                bf[nt][1] = __float_as_uint(sV[vr1 + cc]);
            }
            #pragma unroll
            for (int nt = 0; nt < 8; nt++)
                mma_tf32(o[nt], pa[0], pa[1], pa[2], pa[3], bf[nt][0], bf[nt][1]);
        }
        __syncthreads();
    }

    // epilogue: normalize, store fp16 (feeds Wo GEMM)
    float inv_lo = 1.0f / l_lo;
    float inv_hi = 1.0f / l_hi;
    #pragma unroll
    for (int nt = 0; nt < 8; nt++) {
        int d = nt * 8 + 2 * tg;
        size_t r0 = base + (size_t)(q0 + wq + gid) * DM + d;
        size_t r1 = base + (size_t)(q0 + wq + gid + 8) * DM + d;
        __half2 h0 = __floats2half2_rn(o[nt][0] * inv_lo, o[nt][1] * inv_lo);
        __half2 h1 = __floats2half2_rn(o[nt][2] * inv_hi, o[nt][3] * inv_hi);
        *(uint32_t*)(Oh + r0) = *(uint32_t*)&h0;
        *(uint32_t*)(Oh + r1) = *(uint32_t*)&h1;
    }
}

// ---------------- launcher -------------------------------------------------
extern "C" void kernel_launch(void* const* d_in, const int* in_sizes, int n_in,
                              void* d_out, int out_size)
{
    const float* x      = (const float*)d_in[0];
    const float* Wq     = (const float*)d_in[1];
    const float* bq     = (const float*)d_in[2];
    const float* Wk     = (const float*)d_in[3];
    const float* bk     = (const float*)d_in[4];
    const float* Wv     = (const float*)d_in[5];
    const float* bv     = (const float*)d_in[6];
    const float* Wo     = (const float*)d_in[7];
    const float* bo     = (const float*)d_in[8];
    const float* alpha1 = (const float*)d_in[9];
    const float* beta1  = (const float*)d_in[10];
    const float* alpha2 = (const float*)d_in[11];
    const float* beta2  = (const float*)d_in[12];
    const float* W1     = (const float*)d_in[13];
    const float* b1     = (const float*)d_in[14];
    const float* W2     = (const float*)d_in[15];
    const float* b2     = (const float*)d_in[16];
    float* out = (float*)d_out;

    float *xn, *q, *k, *v, *kt, *x2;
    __half *xnh, *aoh, *hnh, *h1h;
    __half *wqh, *wkh, *wvh, *woh, *w1h, *w2h;
    cudaGetSymbolAddress((void**)&xn,  g_xn);
    cudaGetSymbolAddress((void**)&xnh, g_xnh);
    cudaGetSymbolAddress((void**)&q,   g_q);
    cudaGetSymbolAddress((void**)&k,   g_k);
    cudaGetSymbolAddress((void**)&v,   g_v);
    cudaGetSymbolAddress((void**)&kt,  g_kt);
    cudaGetSymbolAddress((void**)&aoh, g_aoh);
    cudaGetSymbolAddress((void**)&x2,  g_x2);
    cudaGetSymbolAddress((void**)&hnh, g_hnh);
    cudaGetSymbolAddress((void**)&h1h, g_h1h);
    cudaGetSymbolAddress((void**)&wqh, g_wqh);
    cudaGetSymbolAddress((void**)&wkh, g_wkh);
    cudaGetSymbolAddress((void**)&wvh, g_wvh);
    cudaGetSymbolAddress((void**)&woh, g_woh);
    cudaGetSymbolAddress((void**)&w1h, g_w1h);
    cudaGetSymbolAddress((void**)&w2h, g_w2h);

    // 0. fused weight fp16 pre-conversion (one launch)
    wcvt_all<<<(4 * NQ4 + 2 * NF4) / 256, 256>>>(Wq, Wk, Wv, Wo, W1, W2,
                                                 wqh, wkh, wvh, woh, w1h, w2h);

    // 1. x_n = norm1(x): float (residual) + fp16 (GEMM A)
    norm_kernel<<<ROWS, 256>>>(x, alpha1, beta1, xn, xnh);

    // 2. fused Q/K/V projections (fp16 x fp16 -> tf32 float; Q pre-scaled 1/8)
    qkv_gemm4<<<dim3(24, ROWS / 128), 128>>>(xnh, wqh, wkh, wvh, bq, bk, bv, q, k, v);

    // 3. K per-head transpose
    htrans_kernel<<<dim3(SEQ / 64, BATCH * NH), 256>>>(k, kt);

    // 4. attention (tf32, proven; outputs fp16 for Wo GEMM)
    int att_smem = ATT_SMEM_FLOATS * (int)sizeof(float);   // 73728 B
    cudaFuncSetAttribute(attn3_kernel, cudaFuncAttributeMaxDynamicSharedMemorySize, att_smem);
    attn3_kernel<<<dim3(SEQ / 64, BATCH * NH), 128, att_smem>>>(q, kt, v, aoh);

    // 5. x2 = x_n + ao@Wo + bo (fp32 out)
    tgemm4<false, true, 0><<<dim3(DM / 128, ROWS / 128), 128>>>(
        aoh, woh, bo, xn, x2, nullptr, DM, DM);

    // 6. h_n = norm2(x2): fp16 for FFN1 (float copy unused but cheap)
    norm_kernel<<<ROWS, 256>>>(x2, alpha2, beta2, xn, hnh);   // xn reused as dummy float sink

    // 7. h1 = relu(h_n@W1 + b1), fp16 out
    tgemm4<true, false, 2><<<dim3(DFF / 128, ROWS / 128), 128>>>(
        hnh, w1h, b1, nullptr, nullptr, h1h, DFF, DM);

    // 8. out = x2 + h1@W2 + b2 (fp32)
    tgemm4<false, true, 0><<<dim3(DM / 128, ROWS / 128), 128>>>(
        h1h, w2h, b2, x2, out, nullptr, DM, DFF);
}

// round 15
// speedup vs baseline: 2.8585x; 1.3615x over previous
#include <cuda_runtime.h>
#include <cuda_fp16.h>
#include <math.h>
#include <stdint.h>

// Problem constants
#define BATCH 2
#define SEQ   2048
#define DM    1024
#define NH    16
#define DH    64
#define DFF   512
#define ROWS  (BATCH*SEQ)          // 4096

// ---------------- scratch (device globals; no runtime allocation) ----------
__device__ float  g_xn[ROWS*DM];    // norm1(x), tf32-rounded (residual)
__device__ __half g_xnh[ROWS*DM];   // fp16 copy (QKV A)
__device__ __half g_qh[ROWS*DM];    // fp16 Q (pre-scaled by 1/8)
__device__ float  g_k [ROWS*DM];    // fp32 K (pre-htrans)
__device__ __half g_vh[ROWS*DM];    // fp16 V
__device__ __half g_kth[ROWS*DM];   // fp16 K transposed per head [bh][d][s]
__device__ __half g_aoh[ROWS*DM];   // attention output fp16 (Wo A)
__device__ float  g_x2[ROWS*DM];    // xn + attn@Wo + bo (fp32)
__device__ __half g_hnh[ROWS*DM];   // norm2(x2) fp16 (FFN1 A)
__device__ __half g_h1h[ROWS*DFF];  // relu(hn@W1+b1) fp16 (FFN2 A)
// fp16-converted weights
__device__ __half g_wqh[DM*DM];
__device__ __half g_wkh[DM*DM];
__device__ __half g_wvh[DM*DM];
__device__ __half g_woh[DM*DM];
__device__ __half g_w1h[DM*DFF];
__device__ __half g_w2h[DFF*DM];

// ---------------- helpers ---------------------------------------------------
__device__ __forceinline__ float to_tf32(float x) {
    float r;
    asm("cvt.rna.tf32.f32 %0, %1;" : "=f"(r) : "f"(x));
    return r;
}

__device__ __forceinline__ void mma_f16(float c[4],
                                        uint32_t a0, uint32_t a1, uint32_t a2, uint32_t a3,
                                        uint32_t b0, uint32_t b1) {
    asm volatile(
        "mma.sync.aligned.m16n8k16.row.col.f32.f16.f16.f32 "
        "{%0,%1,%2,%3}, {%4,%5,%6,%7}, {%8,%9}, {%0,%1,%2,%3};"
        : "+f"(c[0]), "+f"(c[1]), "+f"(c[2]), "+f"(c[3])
        : "r"(a0), "r"(a1), "r"(a2), "r"(a3), "r"(b0), "r"(b1));
}

__device__ __forceinline__ void ldsm_x4(uint32_t& r0, uint32_t& r1, uint32_t& r2, uint32_t& r3,
                                        uint32_t addr) {
    asm volatile("ldmatrix.sync.aligned.m8n8.x4.shared.b16 {%0,%1,%2,%3}, [%4];"
                 : "=r"(r0), "=r"(r1), "=r"(r2), "=r"(r3) : "r"(addr));
}
__device__ __forceinline__ void ldsm_x4_t(uint32_t& r0, uint32_t& r1, uint32_t& r2, uint32_t& r3,
                                          uint32_t addr) {
    asm volatile("ldmatrix.sync.aligned.m8n8.x4.trans.shared.b16 {%0,%1,%2,%3}, [%4];"
                 : "=r"(r0), "=r"(r1), "=r"(r2), "=r"(r3) : "r"(addr));
}

__device__ __forceinline__ void cp_async16(uint32_t sdst, const void* gsrc) {
    asm volatile("cp.async.cg.shared.global [%0], [%1], 16;"
                 :: "r"(sdst), "l"(gsrc) : "memory");
}
__device__ __forceinline__ void cp_commit() {
    asm volatile("cp.async.commit_group;" ::: "memory");
}
__device__ __forceinline__ void cp_wait1() {
    asm volatile("cp.async.wait_group 1;" ::: "memory");
}
__device__ __forceinline__ void cp_wait0() {
    asm volatile("cp.async.wait_group 0;" ::: "memory");
}

// ---------------- fused weight fp16 pre-conversion (one launch) ------------
#define NQ4 (DM*DM/4)
#define NF4 (DM*DFF/4)
__global__ __launch_bounds__(256)
void wcvt_all(const float* __restrict__ Wq, const float* __restrict__ Wk,
              const float* __restrict__ Wv, const float* __restrict__ Wo,
              const float* __restrict__ W1, const float* __restrict__ W2,
              __half* __restrict__ wq, __half* __restrict__ wk,
              __half* __restrict__ wv, __half* __restrict__ wo,
              __half* __restrict__ w1, __half* __restrict__ w2)
{
    int i = blockIdx.x * 256 + threadIdx.x;
    const float* S; __half* D; int off;
    if (i < 4 * NQ4) {
        int seg = i >> 18;
        off = i & (NQ4 - 1);
        S = (seg == 0) ? Wq : (seg == 1) ? Wk : (seg == 2) ? Wv : Wo;
        D = (seg == 0) ? wq : (seg == 1) ? wk : (seg == 2) ? wv : wo;
    } else {
        int j = i - 4 * NQ4;
        if (j < NF4) { S = W1; D = w1; off = j; }
        else         { S = W2; D = w2; off = j - NF4; }
    }
    float4 v = ((const float4*)S)[off];
    __half2 h01 = __floats2half2_rn(v.x, v.y);
    __half2 h23 = __floats2half2_rn(v.z, v.w);
    uint2 pk = make_uint2(*(uint32_t*)&h01, *(uint32_t*)&h23);
    ((uint2*)D)[off] = pk;
}

// ---------------- NormLayer: float (tf32) + fp16 dual output ---------------
__global__ __launch_bounds__(256)
void norm_kernel(const float* __restrict__ X,
                 const float* __restrict__ alpha,
                 const float* __restrict__ beta,
                 float* __restrict__ Y, __half* __restrict__ Yh)
{
    int row = blockIdx.x;
    int tid = threadIdx.x;
    const float* xr = X + (size_t)row * DM;

    float4 v = *(const float4*)(xr + tid * 4);
    float s  = v.x + v.y + v.z + v.w;
    float sq = v.x*v.x + v.y*v.y + v.z*v.z + v.w*v.w;

    #pragma unroll
    for (int m = 16; m; m >>= 1) {
        s  += __shfl_xor_sync(0xffffffffu, s,  m);
        sq += __shfl_xor_sync(0xffffffffu, sq, m);
    }
    __shared__ float red[16];
    __shared__ float s_mean, s_rstd;
    int wid  = tid >> 5;
    int lane = tid & 31;
    if (lane == 0) { red[wid] = s; red[8 + wid] = sq; }
    __syncthreads();
    if (tid == 0) {
        float S = 0.f, SQ = 0.f;
        #pragma unroll
        for (int w = 0; w < 8; w++) { S += red[w]; SQ += red[8 + w]; }
        float mean = S * (1.0f / DM);
        float var  = (SQ - (float)DM * mean * mean) * (1.0f / (DM - 1));
        s_mean = mean;
        s_rstd = rsqrtf(var + 1e-6f);
    }
    __syncthreads();
    float mean = s_mean, rstd = s_rstd;

    float4 a = *(const float4*)(alpha + tid * 4);
    float4 b = *(const float4*)(beta  + tid * 4);
    float4 o;
    o.x = a.x * (v.x - mean) * rstd + b.x;
    o.y = a.y * (v.y - mean) * rstd + b.y;
    o.z = a.z * (v.z - mean) * rstd + b.z;
    o.w = a.w * (v.w - mean) * rstd + b.w;
    __half2 h01 = __floats2half2_rn(o.x, o.y);
    __half2 h23 = __floats2half2_rn(o.z, o.w);
    *(uint2*)(Yh + (size_t)row * DM + tid * 4) =
        make_uint2(*(uint32_t*)&h01, *(uint32_t*)&h23);
    o.x = to_tf32(o.x); o.y = to_tf32(o.y);
    o.z = to_tf32(o.z); o.w = to_tf32(o.w);
    *(float4*)(Y + (size_t)row * DM + tid * 4) = o;
}

// ---------------- per-head transpose: K float [row][h*64+d] -> fp16 KT -----
__global__ __launch_bounds__(256)
void htrans_h_kernel(const float* __restrict__ X, __half* __restrict__ XTh)
{
    __shared__ float ts[64 * 65];
    int tid = threadIdx.x;
    int bh = blockIdx.y;
    int s0 = blockIdx.x * 64;
    size_t base = (size_t)(bh >> 4) * SEQ * DM + (bh & 15) * DH;

    for (int f = tid; f < 64 * 16; f += 256) {
        int s = f >> 4, c4 = (f & 15) << 2;
        float4 v = *(const float4*)(X + base + (size_t)(s0 + s) * DM + c4);
        ts[s * 65 + c4 + 0] = v.x;
        ts[s * 65 + c4 + 1] = v.y;
        ts[s * 65 + c4 + 2] = v.z;
        ts[s * 65 + c4 + 3] = v.w;
    }
    __syncthreads();
    for (int f = tid; f < 64 * 16; f += 256) {
        int d = f >> 4, s4 = (f & 15) << 2;
        __half2 h01 = __floats2half2_rn(ts[(s4 + 0) * 65 + d], ts[(s4 + 1) * 65 + d]);
        __half2 h23 = __floats2half2_rn(ts[(s4 + 2) * 65 + d], ts[(s4 + 3) * 65 + d]);
        *(uint2*)(XTh + (size_t)(bh * DH + d) * SEQ + s0 + s4) =
            make_uint2(*(uint32_t*)&h01, *(uint32_t*)&h23);
    }
}

// ---------------- tgemm4: fp16 m16n8k16 + ldmatrix, 128x128, 4 warps -------
#define F_SA0 0
#define F_SA1 10240
#define F_SB0 20480
#define F_SB1 29184
#define F_SMEM 37888

// OUT_MODE: 0 = fp32, 1 = tf32-rounded fp32 (x outscale), 2 = fp16 (x outscale)
template<bool RELU, bool HAS_RES, int OUT_MODE>
__device__ __forceinline__ void gemm4_body(
    const __half* __restrict__ A, const __half* __restrict__ B,
    const float* __restrict__ bias, const float* __restrict__ Res,
    float* __restrict__ Cf, __half* __restrict__ Ch,
    int N, int K, int bm, int bn, float outscale)
{
    __shared__ __align__(16) char smc[F_SMEM];
    uint32_t smb = (uint32_t)__cvta_generic_to_shared(smc);

    int tid  = threadIdx.x;
    int warp = tid >> 5, lane = tid & 31;
    int gid  = lane >> 2, tg = lane & 3;
    int wm   = (warp & 1) * 64;
    int wn   = (warp >> 1) * 64;

    int a_row = (lane & 7) + ((lane >> 3) & 1) * 8;
    int a_k   = (lane >> 4) * 8;
    int b_k   = a_row;
    int b_n   = (lane >> 4) * 8;

    const __half* Ab = A + (size_t)(bm * 128) * K;
    const __half* Bb = B + bn * 128;
    int nk = K >> 5;

    #pragma unroll
    for (int i = 0; i < 4; i++) {
        int f = tid + 128 * i;
        int ar = f >> 2, aj = f & 3;
        cp_async16(smb + F_SA0 + (uint32_t)(ar * 80 + aj * 16),
                   Ab + (size_t)ar * K + aj * 8);
        int br = f >> 4, bj = f & 15;
        cp_async16(smb + F_SB0 + (uint32_t)(br * 272 + bj * 16),
                   Bb + (size_t)br * N + bj * 8);
    }
    cp_commit();

    float acc[4][8][4];
    #pragma unroll
    for (int mt = 0; mt < 4; mt++)
        #pragma unroll
        for (int nt = 0; nt < 8; nt++)
            #pragma unroll
            for (int r = 0; r < 4; r++) acc[mt][nt][r] = 0.f;

    for (int kt = 0; kt < nk; kt++) {
        int cur = kt & 1;
        if (kt + 1 < nk) {
            int k0 = (kt + 1) << 5;
            uint32_t sa = cur ? F_SA0 : F_SA1;
            uint32_t sb = cur ? F_SB0 : F_SB1;
            #pragma unroll
            for (int i = 0; i < 4; i++) {
                int f = tid + 128 * i;
                int ar = f >> 2, aj = f & 3;
                cp_async16(smb + sa + (uint32_t)(ar * 80 + aj * 16),
                           Ab + (size_t)ar * K + k0 + aj * 8);
                int br = f >> 4, bj = f & 15;
                cp_async16(smb + sb + (uint32_t)(br * 272 + bj * 16),
                           Bb + (size_t)(k0 + br) * N + bj * 8);
            }
            cp_commit();
            cp_wait1();
        } else {
            cp_wait0();
        }
        __syncthreads();

        uint32_t aBase = smb + (cur ? F_SA1 : F_SA0);
        uint32_t bBase = smb + (cur ? F_SB1 : F_SB0);

        #pragma unroll
        for (int kk = 0; kk < 32; kk += 16) {
            uint32_t af[4][4], bf[8][2];
            #pragma unroll
            for (int mt = 0; mt < 4; mt++) {
                uint32_t addr = aBase + (uint32_t)((wm + mt * 16 + a_row) * 80
                                                   + (kk + a_k) * 2);
                ldsm_x4(af[mt][0], af[mt][1], af[mt][2], af[mt][3], addr);
            }
            #pragma unroll
            for (int nt2 = 0; nt2 < 4; nt2++) {
                uint32_t addr = bBase + (uint32_t)((kk + b_k) * 272
                                                   + (wn + nt2 * 16 + b_n) * 2);
                ldsm_x4_t(bf[nt2 * 2][0], bf[nt2 * 2][1],
                          bf[nt2 * 2 + 1][0], bf[nt2 * 2 + 1][1], addr);
            }
            #pragma unroll
            for (int mt = 0; mt < 4; mt++)
                #pragma unroll
                for (int nt = 0; nt < 8; nt++)
                    mma_f16(acc[mt][nt], af[mt][0], af[mt][1], af[mt][2], af[mt][3],
                            bf[nt][0], bf[nt][1]);
        }
        __syncthreads();
    }

    #pragma unroll
    for (int nt = 0; nt < 8; nt++) {
        int col = bn * 128 + wn + nt * 8 + 2 * tg;
        float2 bv = *(const float2*)(bias + col);
        #pragma unroll
        for (int mt = 0; mt < 4; mt++) {
            int r0 = bm * 128 + wm + mt * 16 + gid;
            int r1 = r0 + 8;
            float2 c0 = make_float2(acc[mt][nt][0] + bv.x, acc[mt][nt][1] + bv.y);
            float2 c1 = make_float2(acc[mt][nt][2] + bv.x, acc[mt][nt][3] + bv.y);
            if (RELU) {
                c0.x = fmaxf(c0.x, 0.f); c0.y = fmaxf(c0.y, 0.f);
                c1.x = fmaxf(c1.x, 0.f); c1.y = fmaxf(c1.y, 0.f);
            }
            if (HAS_RES) {
                float2 r0v = *(const float2*)(Res + (size_t)r0 * N + col);
                float2 r1v = *(const float2*)(Res + (size_t)r1 * N + col);
                c0.x += r0v.x; c0.y += r0v.y;
                c1.x += r1v.x; c1.y += r1v.y;
            }
            if (OUT_MODE == 2) {
                __half2 h0 = __floats2half2_rn(c0.x * outscale, c0.y * outscale);
                __half2 h1 = __floats2half2_rn(c1.x * outscale, c1.y * outscale);
                *(uint32_t*)(Ch + (size_t)r0 * N + col) = *(uint32_t*)&h0;
                *(uint32_t*)(Ch + (size_t)r1 * N + col) = *(uint32_t*)&h1;
            } else {
                if (OUT_MODE == 1) {
                    c0.x = to_tf32(c0.x * outscale); c0.y = to_tf32(c0.y * outscale);
                    c1.x = to_tf32(c1.x * outscale); c1.y = to_tf32(c1.y * outscale);
                }
                *(float2*)(Cf + (size_t)r0 * N + col) = c0;
                *(float2*)(Cf + (size_t)r1 * N + col) = c1;
            }
        }
    }
}

template<bool RELU, bool HAS_RES, int OUT_MODE>
__global__ __launch_bounds__(128)
void tgemm4(const __half* __restrict__ A, const __half* __restrict__ B,
            const float* __restrict__ bias, const float* __restrict__ Res,
            float* __restrict__ Cf, __half* __restrict__ Ch, int N, int K)
{
    gemm4_body<RELU, HAS_RES, OUT_MODE>(A, B, bias, Res, Cf, Ch, N, K,
                                        blockIdx.y, blockIdx.x, 1.0f);
}

// fused QKV: Q -> fp16 x0.125, K -> fp32, V -> fp16
__global__ __launch_bounds__(128)
void qkv_gemm4(const __half* __restrict__ A,
               const __half* __restrict__ Wq, const __half* __restrict__ Wk,
               const __half* __restrict__ Wv,
               const float* __restrict__ bq, const float* __restrict__ bk,
               const float* __restrict__ bv,
               __half* __restrict__ Oqh, float* __restrict__ Okf,
               __half* __restrict__ Ovh)
{
    int sel = blockIdx.x >> 3;
    int bn  = blockIdx.x & 7;
    if (sel == 0) {
        gemm4_body<false, false, 2>(A, Wq, bq, nullptr, nullptr, Oqh, DM, DM,
                                    blockIdx.y, bn, 0.125f);
    } else if (sel == 1) {
        gemm4_body<false, false, 0>(A, Wk, bk, nullptr, Okf, nullptr, DM, DM,
                                    blockIdx.y, bn, 1.0f);
    } else {
        gemm4_body<false, false, 2>(A, Wv, bv, nullptr, nullptr, Ovh, DM, DM,
                                    blockIdx.y, bn, 1.0f);
    }
}

// ---------------- fp16 flash attention: m16n8k16, P in registers -----------
// 128 threads (4 warps), 64 queries/block, 64-key tiles, K^T/V double-buffered.
// smem rows stride 144 B (r*16 mod 128 distinct -> ldmatrix conflict-free).
// smem = 4 x 64 x 144 = 36864 B.
#define HSTR 144
#define SH_K0 0
#define SH_K1 (64 * HSTR)
#define SH_V0 (2 * 64 * HSTR)
#define SH_V1 (3 * 64 * HSTR)
#define ATTH_SMEM (4 * 64 * HSTR)

__global__ __launch_bounds__(128)
void attn_h_kernel(const __half* __restrict__ Qh, const __half* __restrict__ KTh,
                   const __half* __restrict__ Vh, __half* __restrict__ Oh)
{
    extern __shared__ __align__(16) char smc[];
    uint32_t smb = (uint32_t)__cvta_generic_to_shared(smc);

    int tid  = threadIdx.x;
    int warp = tid >> 5, lane = tid & 31;
    int gid  = lane >> 2, tg = lane & 3;
    int wq   = warp * 16;

    int a_row = (lane & 7) + ((lane >> 3) & 1) * 8;
    int a_k   = (lane >> 4) * 8;
    int b_k   = a_row;
    int b_n   = (lane >> 4) * 8;

    int bh = blockIdx.y;
    int q0 = blockIdx.x * 64;
    size_t base   = (size_t)(bh >> 4) * SEQ * DM + (bh & 15) * DH;
    size_t ktbase = (size_t)(bh * DH) * SEQ;

    // loader: f = tid + 128*i -> row = f>>3 (16 rows/pass), 16B col j = f&7
    int lrow = tid >> 3;
    int lj   = tid & 7;

    // ---- stage Q tile (fp16, pre-scaled) into SH_V0 region; extract frags
    #pragma unroll
    for (int i = 0; i < 4; i++) {
        int r = lrow + i * 16;
        cp_async16(smb + SH_V0 + (uint32_t)(r * HSTR + lj * 16),
                   Qh + base + (size_t)(q0 + r) * DM + lj * 8);
    }
    cp_commit();
    cp_wait0();
    __syncthreads();

    uint32_t qf[4][4];
    #pragma unroll
    for (int kc = 0; kc < 4; kc++) {
        uint32_t addr = smb + SH_V0 + (uint32_t)((wq + a_row) * HSTR + (kc * 16 + a_k) * 2);
        ldsm_x4(qf[kc][0], qf[kc][1], qf[kc][2], qf[kc][3], addr);
    }
    __syncthreads();

    float o[8][4];
    #pragma unroll
    for (int dn = 0; dn < 8; dn++)
        #pragma unroll
        for (int r = 0; r < 4; r++) o[dn][r] = 0.f;
    float m_lo = -INFINITY, m_hi = -INFINITY, l_lo = 0.f, l_hi = 0.f;

    const int NT = SEQ / 64;

    // ---- prologue: tile 0 into buffer 0 (one group: K^T + V)
    #pragma unroll
    for (int i = 0; i < 4; i++) {
        int r = lrow + i * 16;
        cp_async16(smb + SH_K0 + (uint32_t)(r * HSTR + lj * 16),
                   KTh + ktbase + (size_t)r * SEQ + lj * 8);
        cp_async16(smb + SH_V0 + (uint32_t)(r * HSTR + lj * 16),
                   Vh + base + (size_t)r * DM + lj * 8);
    }
    cp_commit();

    for (int kt = 0; kt < NT; kt++) {
        int cur = kt & 1;
        if (kt + 1 < NT) {
            int k0n = (kt + 1) * 64;
            uint32_t kdst = smb + (cur ? SH_K0 : SH_K1);
            uint32_t vdst = smb + (cur ? SH_V0 : SH_V1);
            #pragma unroll
            for (int i = 0; i < 4; i++) {
                int r = lrow + i * 16;
                cp_async16(kdst + (uint32_t)(r * HSTR + lj * 16),
                           KTh + ktbase + (size_t)r * SEQ + k0n + lj * 8);
                cp_async16(vdst + (uint32_t)(r * HSTR + lj * 16),
                           Vh + base + (size_t)(k0n + r) * DM + lj * 8);
            }
            cp_commit();
            cp_wait1();
        } else {
            cp_wait0();
        }
        __syncthreads();

        uint32_t ktb = smb + (cur ? SH_K1 : SH_K0);
        uint32_t vtb = smb + (cur ? SH_V1 : SH_V0);

        // ---- S = Q @ K^T  (Q pre-scaled by 1/8); B = KT[d][key]
        float s[8][4];
        #pragma unroll
        for (int nt = 0; nt < 8; nt++)
            #pragma unroll
            for (int r = 0; r < 4; r++) s[nt][r] = 0.f;

        #pragma unroll
        for (int kc = 0; kc < 4; kc++) {
            uint32_t bf[8][2];
            #pragma unroll
            for (int nt2 = 0; nt2 < 4; nt2++) {
                uint32_t addr = ktb + (uint32_t)((kc * 16 + b_k) * HSTR
                                                 + (nt2 * 16 + b_n) * 2);
                ldsm_x4_t(bf[nt2 * 2][0], bf[nt2 * 2][1],
                          bf[nt2 * 2 + 1][0], bf[nt2 * 2 + 1][1], addr);
            }
            #pragma unroll
            for (int nt = 0; nt < 8; nt++)
                mma_f16(s[nt], qf[kc][0], qf[kc][1], qf[kc][2], qf[kc][3],
                        bf[nt][0], bf[nt][1]);
        }

        // ---- online softmax (rows: gid / gid+8)
        float mx_lo = -INFINITY, mx_hi = -INFINITY;
        #pragma unroll
        for (int nt = 0; nt < 8; nt++) {
            mx_lo = fmaxf(mx_lo, fmaxf(s[nt][0], s[nt][1]));
            mx_hi = fmaxf(mx_hi, fmaxf(s[nt][2], s[nt][3]));
        }
        #pragma unroll
        for (int off = 1; off < 4; off <<= 1) {
            mx_lo = fmaxf(mx_lo, __shfl_xor_sync(0xffffffffu, mx_lo, off));
            mx_hi = fmaxf(mx_hi, __shfl_xor_sync(0xffffffffu, mx_hi, off));
        }
        float mn_lo = fmaxf(m_lo, mx_lo);
        float mn_hi = fmaxf(m_hi, mx_hi);
        float al_lo = __expf(m_lo - mn_lo);
        float al_hi = __expf(m_hi - mn_hi);
        float ps_lo = 0.f, ps_hi = 0.f;
        #pragma unroll
        for (int nt = 0; nt < 8; nt++) {
            s[nt][0] = __expf(s[nt][0] - mn_lo);
            s[nt][1] = __expf(s[nt][1] - mn_lo);
            s[nt][2] = __expf(s[nt][2] - mn_hi);
            s[nt][3] = __expf(s[nt][3] - mn_hi);
            ps_lo += s[nt][0] + s[nt][1];
            ps_hi += s[nt][2] + s[nt][3];
        }
        #pragma unroll
        for (int off = 1; off < 4; off <<= 1) {
            ps_lo += __shfl_xor_sync(0xffffffffu, ps_lo, off);
            ps_hi += __shfl_xor_sync(0xffffffffu, ps_hi, off);
        }
        l_lo = l_lo * al_lo + ps_lo;
        l_hi = l_hi * al_hi + ps_hi;
        m_lo = mn_lo; m_hi = mn_hi;
        #pragma unroll
        for (int dn = 0; dn < 8; dn++) {
            o[dn][0] *= al_lo; o[dn][1] *= al_lo;
            o[dn][2] *= al_hi; o[dn][3] *= al_hi;
        }

        // ---- O += P @ V : P C-frags repack directly into A-frags (fp16)
        #pragma unroll
        for (int kc = 0; kc < 4; kc++) {
            __half2 h;
            uint32_t a0, a1, a2, a3;
            h = __floats2half2_rn(s[2 * kc][0],     s[2 * kc][1]);     a0 = *(uint32_t*)&h;
            h = __floats2half2_rn(s[2 * kc][2],     s[2 * kc][3]);     a1 = *(uint32_t*)&h;
            h = __floats2half2_rn(s[2 * kc + 1][0], s[2 * kc + 1][1]); a2 = *(uint32_t*)&h;
            h = __floats2half2_rn(s[2 * kc + 1][2], s[2 * kc + 1][3]); a3 = *(uint32_t*)&h;

            uint32_t bf[8][2];
            #pragma unroll
            for (int nt2 = 0; nt2 < 4; nt2++) {
                uint32_t addr = vtb + (uint32_t)((kc * 16 + b_k) * HSTR
                                                 + (nt2 * 16 + b_n) * 2);
                ldsm_x4_t(bf[nt2 * 2][0], bf[nt2 * 2][1],
                          bf[nt2 * 2 + 1][0], bf[nt2 * 2 + 1][1], addr);
            }
            #pragma unroll
            for (int dn = 0; dn < 8; dn++)
                mma_f16(o[dn], a0, a1, a2, a3, bf[dn][0], bf[dn][1]);
        }
        __syncthreads();   // reads done before next iteration overwrites buffers
    }

    // ---- epilogue: normalize, store fp16 (feeds Wo GEMM)
    float inv_lo = 1.0f / l_lo;
    float inv_hi = 1.0f / l_hi;
    #pragma unroll
    for (int dn = 0; dn < 8; dn++) {
        int d = dn * 8 + 2 * tg;
        size_t r0 = base + (size_t)(q0 + wq + gid) * DM + d;
        size_t r1 = base + (size_t)(q0 + wq + gid + 8) * DM + d;
        __half2 h0 = __floats2half2_rn(o[dn][0] * inv_lo, o[dn][1] * inv_lo);
        __half2 h1 = __floats2half2_rn(o[dn][2] * inv_hi, o[dn][3] * inv_hi);
        *(uint32_t*)(Oh + r0) = *(uint32_t*)&h0;
        *(uint32_t*)(Oh + r1) = *(uint32_t*)&h1;
    }
}

// ---------------- launcher -------------------------------------------------
extern "C" void kernel_launch(void* const* d_in, const int* in_sizes, int n_in,
                              void* d_out, int out_size)
{
    const float* x      = (const float*)d_in[0];
    const float* Wq     = (const float*)d_in[1];
    const float* bq     = (const float*)d_in[2];
    const float* Wk     = (const float*)d_in[3];
    const float* bk     = (const float*)d_in[4];
    const float* Wv     = (const float*)d_in[5];
    const float* bv     = (const float*)d_in[6];
    const float* Wo     = (const float*)d_in[7];
    const float* bo     = (const float*)d_in[8];
    const float* alpha1 = (const float*)d_in[9];
    const float* beta1  = (const float*)d_in[10];
    const float* alpha2 = (const float*)d_in[11];
    const float* beta2  = (const float*)d_in[12];
    const float* W1     = (const float*)d_in[13];
    const float* b1     = (const float*)d_in[14];
    const float* W2     = (const float*)d_in[15];
    const float* b2     = (const float*)d_in[16];
    float* out = (float*)d_out;

    float *xn, *k, *x2;
    __half *xnh, *qh, *vh, *kth, *aoh, *hnh, *h1h;
    __half *wqh, *wkh, *wvh, *woh, *w1h, *w2h;
    cudaGetSymbolAddress((void**)&xn,  g_xn);
    cudaGetSymbolAddress((void**)&xnh, g_xnh);
    cudaGetSymbolAddress((void**)&qh,  g_qh);
    cudaGetSymbolAddress((void**)&k,   g_k);
    cudaGetSymbolAddress((void**)&vh,  g_vh);
    cudaGetSymbolAddress((void**)&kth, g_kth);
    cudaGetSymbolAddress((void**)&aoh, g_aoh);
    cudaGetSymbolAddress((void**)&x2,  g_x2);
    cudaGetSymbolAddress((void**)&hnh, g_hnh);
    cudaGetSymbolAddress((void**)&h1h, g_h1h);
    cudaGetSymbolAddress((void**)&wqh, g_wqh);
    cudaGetSymbolAddress((void**)&wkh, g_wkh);
    cudaGetSymbolAddress((void**)&wvh, g_wvh);
    cudaGetSymbolAddress((void**)&woh, g_woh);
    cudaGetSymbolAddress((void**)&w1h, g_w1h);
    cudaGetSymbolAddress((void**)&w2h, g_w2h);

    // 0. fused weight fp16 pre-conversion
    wcvt_all<<<(4 * NQ4 + 2 * NF4) / 256, 256>>>(Wq, Wk, Wv, Wo, W1, W2,
                                                 wqh, wkh, wvh, woh, w1h, w2h);

    // 1. x_n = norm1(x): float (residual) + fp16 (GEMM A)
    norm_kernel<<<ROWS, 256>>>(x, alpha1, beta1, xn, xnh);

    // 2. fused Q/K/V projections (Q fp16 x1/8, K fp32, V fp16)
    qkv_gemm4<<<dim3(24, ROWS / 128), 128>>>(xnh, wqh, wkh, wvh, bq, bk, bv,
                                             qh, k, vh);

    // 3. K per-head transpose + fp16 convert
    htrans_h_kernel<<<dim3(SEQ / 64, BATCH * NH), 256>>>(k, kth);

    // 4. fp16 flash attention
    cudaFuncSetAttribute(attn_h_kernel, cudaFuncAttributeMaxDynamicSharedMemorySize, ATTH_SMEM);
    attn_h_kernel<<<dim3(SEQ / 64, BATCH * NH), 128, ATTH_SMEM>>>(qh, kth, vh, aoh);

    // 5. x2 = x_n + ao@Wo + bo (fp32 out)
    tgemm4<false, true, 0><<<dim3(DM / 128, ROWS / 128), 128>>>(
        aoh, woh, bo, xn, x2, nullptr, DM, DM);

    // 6. h_n = norm2(x2): fp16 for FFN1
    norm_kernel<<<ROWS, 256>>>(x2, alpha2, beta2, xn, hnh);

    // 7. h1 = relu(h_n@W1 + b1), fp16 out
    tgemm4<true, false, 2><<<dim3(DFF / 128, ROWS / 128), 128>>>(
        hnh, w1h, b1, nullptr, nullptr, h1h, DFF, DM);

    // 8. out = x2 + h1@W2 + b2 (fp32)
    tgemm4<false, true, 0><<<dim3(DM / 128, ROWS / 128), 128>>>(
        h1h, w2h, b2, x2, out, nullptr, DM, DFF);
}

// round 16
// speedup vs baseline: 3.1643x; 1.1070x over previous
#include <cuda_runtime.h>
#include <cuda_fp16.h>
#include <math.h>
#include <stdint.h>

// Problem constants
#define BATCH 2
#define SEQ   2048
#define DM    1024
#define NH    16
#define DH    64
#define DFF   512
#define ROWS  (BATCH*SEQ)          // 4096

// ---------------- scratch (device globals; no runtime allocation) ----------
__device__ float  g_xn[ROWS*DM];    // norm1(x), tf32-rounded (residual)
__device__ __half g_xnh[ROWS*DM];   // fp16 copy (QKV A)
__device__ __half g_qh[ROWS*DM];    // fp16 Q (pre-scaled by 1/8)
__device__ __half g_kh[ROWS*DM];    // fp16 K (pre-htrans)
__device__ __half g_vh[ROWS*DM];    // fp16 V
__device__ __half g_kth[ROWS*DM];   // fp16 K transposed per head [bh][d][s]
__device__ __half g_aoh[ROWS*DM];   // attention output fp16 (Wo A)
__device__ float  g_x2[ROWS*DM];    // xn + attn@Wo + bo (fp32)
__device__ __half g_hnh[ROWS*DM];   // norm2(x2) fp16 (FFN1 A)
__device__ __half g_h1h[ROWS*DFF];  // relu(hn@W1+b1) fp16 (FFN2 A)
// fp16-converted weights
__device__ __half g_wqh[DM*DM];
__device__ __half g_wkh[DM*DM];
__device__ __half g_wvh[DM*DM];
__device__ __half g_woh[DM*DM];
__device__ __half g_w1h[DM*DFF];
__device__ __half g_w2h[DFF*DM];

// ---------------- helpers ---------------------------------------------------
__device__ __forceinline__ float to_tf32(float x) {
    float r;
    asm("cvt.rna.tf32.f32 %0, %1;" : "=f"(r) : "f"(x));
    return r;
}

__device__ __forceinline__ void mma_f16(float c[4],
                                        uint32_t a0, uint32_t a1, uint32_t a2, uint32_t a3,
                                        uint32_t b0, uint32_t b1) {
    asm volatile(
        "mma.sync.aligned.m16n8k16.row.col.f32.f16.f16.f32 "
        "{%0,%1,%2,%3}, {%4,%5,%6,%7}, {%8,%9}, {%0,%1,%2,%3};"
        : "+f"(c[0]), "+f"(c[1]), "+f"(c[2]), "+f"(c[3])
        : "r"(a0), "r"(a1), "r"(a2), "r"(a3), "r"(b0), "r"(b1));
}

__device__ __forceinline__ void ldsm_x4(uint32_t& r0, uint32_t& r1, uint32_t& r2, uint32_t& r3,
                                        uint32_t addr) {
    asm volatile("ldmatrix.sync.aligned.m8n8.x4.shared.b16 {%0,%1,%2,%3}, [%4];"
                 : "=r"(r0), "=r"(r1), "=r"(r2), "=r"(r3) : "r"(addr));
}
__device__ __forceinline__ void ldsm_x4_t(uint32_t& r0, uint32_t& r1, uint32_t& r2, uint32_t& r3,
                                          uint32_t addr) {
    asm volatile("ldmatrix.sync.aligned.m8n8.x4.trans.shared.b16 {%0,%1,%2,%3}, [%4];"
                 : "=r"(r0), "=r"(r1), "=r"(r2), "=r"(r3) : "r"(addr));
}

__device__ __forceinline__ void cp_async16(uint32_t sdst, const void* gsrc) {
    asm volatile("cp.async.cg.shared.global [%0], [%1], 16;"
                 :: "r"(sdst), "l"(gsrc) : "memory");
}
__device__ __forceinline__ void cp_commit() {
    asm volatile("cp.async.commit_group;" ::: "memory");
}
__device__ __forceinline__ void cp_wait1() {
    asm volatile("cp.async.wait_group 1;" ::: "memory");
}
__device__ __forceinline__ void cp_wait0() {
    asm volatile("cp.async.wait_group 0;" ::: "memory");
}

// ---------------- fused weight fp16 pre-conversion (one launch) ------------
#define NQ4 (DM*DM/4)
#define NF4 (DM*DFF/4)
__global__ __launch_bounds__(256)
void wcvt_all(const float* __restrict__ Wq, const float* __restrict__ Wk,
              const float* __restrict__ Wv, const float* __restrict__ Wo,
              const float* __restrict__ W1, const float* __restrict__ W2,
              __half* __restrict__ wq, __half* __restrict__ wk,
              __half* __restrict__ wv, __half* __restrict__ wo,
              __half* __restrict__ w1, __half* __restrict__ w2)
{
    int i = blockIdx.x * 256 + threadIdx.x;
    const float* S; __half* D; int off;
    if (i < 4 * NQ4) {
        int seg = i >> 18;
        off = i & (NQ4 - 1);
        S = (seg == 0) ? Wq : (seg == 1) ? Wk : (seg == 2) ? Wv : Wo;
        D = (seg == 0) ? wq : (seg == 1) ? wk : (seg == 2) ? wv : wo;
    } else {
        int j = i - 4 * NQ4;
        if (j < NF4) { S = W1; D = w1; off = j; }
        else         { S = W2; D = w2; off = j - NF4; }
    }
    float4 v = ((const float4*)S)[off];
    __half2 h01 = __floats2half2_rn(v.x, v.y);
    __half2 h23 = __floats2half2_rn(v.z, v.w);
    uint2 pk = make_uint2(*(uint32_t*)&h01, *(uint32_t*)&h23);
    ((uint2*)D)[off] = pk;
}

// ---------------- NormLayer: fp16 out; optional tf32 float out -------------
template<bool WRITE_F>
__global__ __launch_bounds__(256)
void norm_kernel(const float* __restrict__ X,
                 const float* __restrict__ alpha,
                 const float* __restrict__ beta,
                 float* __restrict__ Y, __half* __restrict__ Yh)
{
    int row = blockIdx.x;
    int tid = threadIdx.x;
    const float* xr = X + (size_t)row * DM;

    float4 v = *(const float4*)(xr + tid * 4);
    float s  = v.x + v.y + v.z + v.w;
    float sq = v.x*v.x + v.y*v.y + v.z*v.z + v.w*v.w;

    #pragma unroll
    for (int m = 16; m; m >>= 1) {
        s  += __shfl_xor_sync(0xffffffffu, s,  m);
        sq += __shfl_xor_sync(0xffffffffu, sq, m);
    }
    __shared__ float red[16];
    __shared__ float s_mean, s_rstd;
    int wid  = tid >> 5;
    int lane = tid & 31;
    if (lane == 0) { red[wid] = s; red[8 + wid] = sq; }
    __syncthreads();
    if (tid == 0) {
        float S = 0.f, SQ = 0.f;
        #pragma unroll
        for (int w = 0; w < 8; w++) { S += red[w]; SQ += red[8 + w]; }
        float mean = S * (1.0f / DM);
        float var  = (SQ - (float)DM * mean * mean) * (1.0f / (DM - 1));
        s_mean = mean;
        s_rstd = rsqrtf(var + 1e-6f);
    }
    __syncthreads();
    float mean = s_mean, rstd = s_rstd;

    float4 a = *(const float4*)(alpha + tid * 4);
    float4 b = *(const float4*)(beta  + tid * 4);
    float4 o;
    o.x = a.x * (v.x - mean) * rstd + b.x;
    o.y = a.y * (v.y - mean) * rstd + b.y;
    o.z = a.z * (v.z - mean) * rstd + b.z;
    o.w = a.w * (v.w - mean) * rstd + b.w;
    __half2 h01 = __floats2half2_rn(o.x, o.y);
    __half2 h23 = __floats2half2_rn(o.z, o.w);
    *(uint2*)(Yh + (size_t)row * DM + tid * 4) =
        make_uint2(*(uint32_t*)&h01, *(uint32_t*)&h23);
    if (WRITE_F) {
        o.x = to_tf32(o.x); o.y = to_tf32(o.y);
        o.z = to_tf32(o.z); o.w = to_tf32(o.w);
        *(float4*)(Y + (size_t)row * DM + tid * 4) = o;
    }
}

// ---------------- per-head transpose: K fp16 [row][h*64+d] -> fp16 KT ------
__global__ __launch_bounds__(256)
void htrans_h_kernel(const __half* __restrict__ Xh, __half* __restrict__ XTh)
{
    __shared__ float ts[64 * 65];
    int tid = threadIdx.x;
    int bh = blockIdx.y;
    int s0 = blockIdx.x * 64;
    size_t base = (size_t)(bh >> 4) * SEQ * DM + (bh & 15) * DH;

    for (int f = tid; f < 64 * 16; f += 256) {
        int s = f >> 4, c4 = (f & 15) << 2;
        uint2 hv = *(const uint2*)(Xh + base + (size_t)(s0 + s) * DM + c4);
        __half2 h01 = *(__half2*)&hv.x;
        __half2 h23 = *(__half2*)&hv.y;
        ts[s * 65 + c4 + 0] = __low2float(h01);
        ts[s * 65 + c4 + 1] = __high2float(h01);
        ts[s * 65 + c4 + 2] = __low2float(h23);
        ts[s * 65 + c4 + 3] = __high2float(h23);
    }
    __syncthreads();
    for (int f = tid; f < 64 * 16; f += 256) {
        int d = f >> 4, s4 = (f & 15) << 2;
        __half2 h01 = __floats2half2_rn(ts[(s4 + 0) * 65 + d], ts[(s4 + 1) * 65 + d]);
        __half2 h23 = __floats2half2_rn(ts[(s4 + 2) * 65 + d], ts[(s4 + 3) * 65 + d]);
        *(uint2*)(XTh + (size_t)(bh * DH + d) * SEQ + s0 + s4) =
            make_uint2(*(uint32_t*)&h01, *(uint32_t*)&h23);
    }
}

// ---------------- tgemm5: fp16 m16n8k16 + ldmatrix, 3-stage pipeline -------
// sA: 128 x 80 B = 10240 B/buf; sB: 32 x 272 B = 8704 B/buf; 3 bufs = 56832 B
#define F3A(i) ((i) * 10240)
#define F3B(i) (30720 + (i) * 8704)
#define F3_SMEM 56832

// OUT_MODE: 0 = fp32, 1 = tf32-rounded fp32 (x outscale), 2 = fp16 (x outscale)
template<bool RELU, bool HAS_RES, int OUT_MODE>
__device__ __forceinline__ void gemm5_body(
    const __half* __restrict__ A, const __half* __restrict__ B,
    const float* __restrict__ bias, const float* __restrict__ Res,
    float* __restrict__ Cf, __half* __restrict__ Ch,
    int N, int K, int bm, int bn, float outscale)
{
    __shared__ __align__(16) char smc[F3_SMEM];
    uint32_t smb = (uint32_t)__cvta_generic_to_shared(smc);

    int tid  = threadIdx.x;
    int warp = tid >> 5, lane = tid & 31;
    int gid  = lane >> 2, tg = lane & 3;
    int wm   = (warp & 1) * 64;
    int wn   = (warp >> 1) * 64;

    int a_row = (lane & 7) + ((lane >> 3) & 1) * 8;
    int a_k   = (lane >> 4) * 8;
    int b_k   = a_row;
    int b_n   = (lane >> 4) * 8;

    const __half* Ab = A + (size_t)(bm * 128) * K;
    const __half* Bb = B + bn * 128;
    int nk = K >> 5;

    // issue group for chunk c into buffer b
    auto issue = [&](int c, int b) {
        int k0 = c << 5;
        #pragma unroll
        for (int i = 0; i < 4; i++) {
            int f = tid + 128 * i;
            int ar = f >> 2, aj = f & 3;
            cp_async16(smb + F3A(b) + (uint32_t)(ar * 80 + aj * 16),
                       Ab + (size_t)ar * K + k0 + aj * 8);
            int br = f >> 4, bj = f & 15;
            cp_async16(smb + F3B(b) + (uint32_t)(br * 272 + bj * 16),
                       Bb + (size_t)(k0 + br) * N + bj * 8);
        }
        cp_commit();
    };

    issue(0, 0);
    if (nk > 1) issue(1, 1);

    float acc[4][8][4];
    #pragma unroll
    for (int mt = 0; mt < 4; mt++)
        #pragma unroll
        for (int nt = 0; nt < 8; nt++)
            #pragma unroll
            for (int r = 0; r < 4; r++) acc[mt][nt][r] = 0.f;

    int buf = 0;
    for (int kt = 0; kt < nk; kt++) {
        if (kt + 1 < nk) cp_wait1(); else cp_wait0();
        __syncthreads();
        if (kt + 2 < nk) issue(kt + 2, (buf + 2) % 3);

        uint32_t aBase = smb + F3A(buf);
        uint32_t bBase = smb + F3B(buf);

        #pragma unroll
        for (int kk = 0; kk < 32; kk += 16) {
            uint32_t af[4][4], bf[8][2];
            #pragma unroll
            for (int mt = 0; mt < 4; mt++) {
                uint32_t addr = aBase + (uint32_t)((wm + mt * 16 + a_row) * 80
                                                   + (kk + a_k) * 2);
                ldsm_x4(af[mt][0], af[mt][1], af[mt][2], af[mt][3], addr);
            }
            #pragma unroll
            for (int nt2 = 0; nt2 < 4; nt2++) {
                uint32_t addr = bBase + (uint32_t)((kk + b_k) * 272
                                                   + (wn + nt2 * 16 + b_n) * 2);
                ldsm_x4_t(bf[nt2 * 2][0], bf[nt2 * 2][1],
                          bf[nt2 * 2 + 1][0], bf[nt2 * 2 + 1][1], addr);
            }
            #pragma unroll
            for (int mt = 0; mt < 4; mt++)
                #pragma unroll
                for (int nt = 0; nt < 8; nt++)
                    mma_f16(acc[mt][nt], af[mt][0], af[mt][1], af[mt][2], af[mt][3],
                            bf[nt][0], bf[nt][1]);
        }
        buf = (buf + 1) % 3;
    }

    #pragma unroll
    for (int nt = 0; nt < 8; nt++) {
        int col = bn * 128 + wn + nt * 8 + 2 * tg;
        float2 bv = *(const float2*)(bias + col);
        #pragma unroll
        for (int mt = 0; mt < 4; mt++) {
            int r0 = bm * 128 + wm + mt * 16 + gid;
            int r1 = r0 + 8;
            float2 c0 = make_float2(acc[mt][nt][0] + bv.x, acc[mt][nt][1] + bv.y);
            float2 c1 = make_float2(acc[mt][nt][2] + bv.x, acc[mt][nt][3] + bv.y);
            if (RELU) {
                c0.x = fmaxf(c0.x, 0.f); c0.y = fmaxf(c0.y, 0.f);
                c1.x = fmaxf(c1.x, 0.f); c1.y = fmaxf(c1.y, 0.f);
            }
            if (HAS_RES) {
                float2 r0v = *(const float2*)(Res + (size_t)r0 * N + col);
                float2 r1v = *(const float2*)(Res + (size_t)r1 * N + col);
                c0.x += r0v.x; c0.y += r0v.y;
                c1.x += r1v.x; c1.y += r1v.y;
            }
            if (OUT_MODE == 2) {
                __half2 h0 = __floats2half2_rn(c0.x * outscale, c0.y * outscale);
                __half2 h1 = __floats2half2_rn(c1.x * outscale, c1.y * outscale);
                *(uint32_t*)(Ch + (size_t)r0 * N + col) = *(uint32_t*)&h0;
                *(uint32_t*)(Ch + (size_t)r1 * N + col) = *(uint32_t*)&h1;
            } else {
                if (OUT_MODE == 1) {
                    c0.x = to_tf32(c0.x * outscale); c0.y = to_tf32(c0.y * outscale);
                    c1.x = to_tf32(c1.x * outscale); c1.y = to_tf32(c1.y * outscale);
                }
                *(float2*)(Cf + (size_t)r0 * N + col) = c0;
                *(float2*)(Cf + (size_t)r1 * N + col) = c1;
            }
        }
    }
}

template<bool RELU, bool HAS_RES, int OUT_MODE>
__global__ __launch_bounds__(128)
void tgemm5(const __half* __restrict__ A, const __half* __restrict__ B,
            const float* __restrict__ bias, const float* __restrict__ Res,
            float* __restrict__ Cf, __half* __restrict__ Ch, int N, int K)
{
    gemm5_body<RELU, HAS_RES, OUT_MODE>(A, B, bias, Res, Cf, Ch, N, K,
                                        blockIdx.y, blockIdx.x, 1.0f);
}

// fused QKV: Q -> fp16 x0.125, K -> fp16, V -> fp16
__global__ __launch_bounds__(128)
void qkv_gemm5(const __half* __restrict__ A,
               const __half* __restrict__ Wq, const __half* __restrict__ Wk,
               const __half* __restrict__ Wv,
               const float* __restrict__ bq, const float* __restrict__ bk,
               const float* __restrict__ bv,
               __half* __restrict__ Oqh, __half* __restrict__ Okh,
               __half* __restrict__ Ovh)
{
    int sel = blockIdx.x >> 3;
    int bn  = blockIdx.x & 7;
    const __half* B   = (sel == 0) ? Wq : (sel == 1) ? Wk : Wv;
    const float* bias = (sel == 0) ? bq : (sel == 1) ? bk : bv;
    __half* C         = (sel == 0) ? Oqh : (sel == 1) ? Okh : Ovh;
    float outscale    = (sel == 0) ? 0.125f : 1.0f;
    gemm5_body<false, false, 2>(A, B, bias, nullptr, nullptr, C, DM, DM,
                                blockIdx.y, bn, outscale);
}

// ---------------- fp16 flash attention: 3-stage pipeline -------------------
// 128 threads (4 warps), 64 queries/block, 64-key tiles.
// Buffers: K0..K2 then V0..V2, 64 x 144 B each; total 55296 B.
#define HSTR 144
#define SH3K(i) ((i) * 9216)
#define SH3V(i) (27648 + (i) * 9216)
#define ATTH_SMEM 55296

__global__ __launch_bounds__(128)
void attn_h_kernel(const __half* __restrict__ Qh, const __half* __restrict__ KTh,
                   const __half* __restrict__ Vh, __half* __restrict__ Oh)
{
    extern __shared__ __align__(16) char smc[];
    uint32_t smb = (uint32_t)__cvta_generic_to_shared(smc);

    int tid  = threadIdx.x;
    int warp = tid >> 5, lane = tid & 31;
    int gid  = lane >> 2, tg = lane & 3;
    int wq   = warp * 16;

    int a_row = (lane & 7) + ((lane >> 3) & 1) * 8;
    int a_k   = (lane >> 4) * 8;
    int b_k   = a_row;
    int b_n   = (lane >> 4) * 8;

    int bh = blockIdx.y;
    int q0 = blockIdx.x * 64;
    size_t base   = (size_t)(bh >> 4) * SEQ * DM + (bh & 15) * DH;
    size_t ktbase = (size_t)(bh * DH) * SEQ;

    int lrow = tid >> 3;
    int lj   = tid & 7;

    // ---- stage Q tile into V0 region; extract fragments
    #pragma unroll
    for (int i = 0; i < 4; i++) {
        int r = lrow + i * 16;
        cp_async16(smb + SH3V(0) + (uint32_t)(r * HSTR + lj * 16),
                   Qh + base + (size_t)(q0 + r) * DM + lj * 8);
    }
    cp_commit();
    cp_wait0();
    __syncthreads();

    uint32_t qf[4][4];
    #pragma unroll
    for (int kc = 0; kc < 4; kc++) {
        uint32_t addr = smb + SH3V(0) + (uint32_t)((wq + a_row) * HSTR + (kc * 16 + a_k) * 2);
        ldsm_x4(qf[kc][0], qf[kc][1], qf[kc][2], qf[kc][3], addr);
    }
    __syncthreads();

    float o[8][4];
    #pragma unroll
    for (int dn = 0; dn < 8; dn++)
        #pragma unroll
        for (int r = 0; r < 4; r++) o[dn][r] = 0.f;
    float m_lo = -INFINITY, m_hi = -INFINITY, l_lo = 0.f, l_hi = 0.f;

    const int NT = SEQ / 64;

    auto issue_tile = [&](int t, int b) {
        int k0n = t * 64;
        uint32_t kdst = smb + SH3K(b);
        uint32_t vdst = smb + SH3V(b);
        #pragma unroll
        for (int i = 0; i < 4; i++) {
            int r = lrow + i * 16;
            cp_async16(kdst + (uint32_t)(r * HSTR + lj * 16),
                       KTh + ktbase + (size_t)r * SEQ + k0n + lj * 8);
            cp_async16(vdst + (uint32_t)(r * HSTR + lj * 16),
                       Vh + base + (size_t)(k0n + r) * DM + lj * 8);
        }
        cp_commit();
    };

    issue_tile(0, 0);
    issue_tile(1, 1);

    int buf = 0;
    for (int kt = 0; kt < NT; kt++) {
        if (kt + 1 < NT) cp_wait1(); else cp_wait0();
        __syncthreads();
        if (kt + 2 < NT) issue_tile(kt + 2, (buf + 2) % 3);

        uint32_t ktb = smb + SH3K(buf);
        uint32_t vtb = smb + SH3V(buf);

        // ---- S = Q @ K^T  (Q pre-scaled by 1/8)
        float s[8][4];
        #pragma unroll
        for (int nt = 0; nt < 8; nt++)
            #pragma unroll
            for (int r = 0; r < 4; r++) s[nt][r] = 0.f;

        #pragma unroll
        for (int kc = 0; kc < 4; kc++) {
            uint32_t bf[8][2];
            #pragma unroll
            for (int nt2 = 0; nt2 < 4; nt2++) {
                uint32_t addr = ktb + (uint32_t)((kc * 16 + b_k) * HSTR
                                                 + (nt2 * 16 + b_n) * 2);
                ldsm_x4_t(bf[nt2 * 2][0], bf[nt2 * 2][1],
                          bf[nt2 * 2 + 1][0], bf[nt2 * 2 + 1][1], addr);
            }
            #pragma unroll
            for (int nt = 0; nt < 8; nt++)
                mma_f16(s[nt], qf[kc][0], qf[kc][1], qf[kc][2], qf[kc][3],
                        bf[nt][0], bf[nt][1]);
        }

        // ---- online softmax
        float mx_lo = -INFINITY, mx_hi = -INFINITY;
        #pragma unroll
        for (int nt = 0; nt < 8; nt++) {
            mx_lo = fmaxf(mx_lo, fmaxf(s[nt][0], s[nt][1]));
            mx_hi = fmaxf(mx_hi, fmaxf(s[nt][2], s[nt][3]));
        }
        #pragma unroll
        for (int off = 1; off < 4; off <<= 1) {
            mx_lo = fmaxf(mx_lo, __shfl_xor_sync(0xffffffffu, mx_lo, off));
            mx_hi = fmaxf(mx_hi, __shfl_xor_sync(0xffffffffu, mx_hi, off));
        }
        float mn_lo = fmaxf(m_lo, mx_lo);
        float mn_hi = fmaxf(m_hi, mx_hi);
        float al_lo = __expf(m_lo - mn_lo);
        float al_hi = __expf(m_hi - mn_hi);
        float ps_lo = 0.f, ps_hi = 0.f;
        #pragma unroll
        for (int nt = 0; nt < 8; nt++) {
            s[nt][0] = __expf(s[nt][0] - mn_lo);
            s[nt][1] = __expf(s[nt][1] - mn_lo);
            s[nt][2] = __expf(s[nt][2] - mn_hi);
            s[nt][3] = __expf(s[nt][3] - mn_hi);
            ps_lo += s[nt][0] + s[nt][1];
            ps_hi += s[nt][2] + s[nt][3];
        }
        #pragma unroll
        for (int off = 1; off < 4; off <<= 1) {
            ps_lo += __shfl_xor_sync(0xffffffffu, ps_lo, off);
            ps_hi += __shfl_xor_sync(0xffffffffu, ps_hi, off);
        }
        l_lo = l_lo * al_lo + ps_lo;
        l_hi = l_hi * al_hi + ps_hi;
        m_lo = mn_lo; m_hi = mn_hi;
        #pragma unroll
        for (int dn = 0; dn < 8; dn++) {
            o[dn][0] *= al_lo; o[dn][1] *= al_lo;
            o[dn][2] *= al_hi; o[dn][3] *= al_hi;
        }

        // ---- O += P @ V : P C-frags repack directly into A-frags
        #pragma unroll
        for (int kc = 0; kc < 4; kc++) {
            __half2 h;
            uint32_t a0, a1, a2, a3;
            h = __floats2half2_rn(s[2 * kc][0],     s[2 * kc][1]);     a0 = *(uint32_t*)&h;
            h = __floats2half2_rn(s[2 * kc][2],     s[2 * kc][3]);     a1 = *(uint32_t*)&h;
            h = __floats2half2_rn(s[2 * kc + 1][0], s[2 * kc + 1][1]); a2 = *(uint32_t*)&h;
            h = __floats2half2_rn(s[2 * kc + 1][2], s[2 * kc + 1][3]); a3 = *(uint32_t*)&h;

            uint32_t bf[8][2];
            #pragma unroll
            for (int nt2 = 0; nt2 < 4; nt2++) {
                uint32_t addr = vtb + (uint32_t)((kc * 16 + b_k) * HSTR
                                                 + (nt2 * 16 + b_n) * 2);
                ldsm_x4_t(bf[nt2 * 2][0], bf[nt2 * 2][1],
                          bf[nt2 * 2 + 1][0], bf[nt2 * 2 + 1][1], addr);
            }
            #pragma unroll
            for (int dn = 0; dn < 8; dn++)
                mma_f16(o[dn], a0, a1, a2, a3, bf[dn][0], bf[dn][1]);
        }
        buf = (buf + 1) % 3;
    }

    // ---- epilogue: normalize, store fp16 (feeds Wo GEMM)
    float inv_lo = 1.0f / l_lo;
    float inv_hi = 1.0f / l_hi;
    #pragma unroll
    for (int dn = 0; dn < 8; dn++) {
        int d = dn * 8 + 2 * tg;
        size_t r0 = base + (size_t)(q0 + wq + gid) * DM + d;
        size_t r1 = base + (size_t)(q0 + wq + gid + 8) * DM + d;
        __half2 h0 = __floats2half2_rn(o[dn][0] * inv_lo, o[dn][1] * inv_lo);
        __half2 h1 = __floats2half2_rn(o[dn][2] * inv_hi, o[dn][3] * inv_hi);
        *(uint32_t*)(Oh + r0) = *(uint32_t*)&h0;
        *(uint32_t*)(Oh + r1) = *(uint32_t*)&h1;
    }
}

// ---------------- launcher -------------------------------------------------
extern "C" void kernel_launch(void* const* d_in, const int* in_sizes, int n_in,
                              void* d_out, int out_size)
{
    const float* x      = (const float*)d_in[0];
    const float* Wq     = (const float*)d_in[1];
    const float* bq     = (const float*)d_in[2];
    const float* Wk     = (const float*)d_in[3];
    const float* bk     = (const float*)d_in[4];
    const float* Wv     = (const float*)d_in[5];
    const float* bv     = (const float*)d_in[6];
    const float* Wo     = (const float*)d_in[7];
    const float* bo     = (const float*)d_in[8];
    const float* alpha1 = (const float*)d_in[9];
    const float* beta1  = (const float*)d_in[10];
    const float* alpha2 = (const float*)d_in[11];
    const float* beta2  = (const float*)d_in[12];
    const float* W1     = (const float*)d_in[13];
    const float* b1     = (const float*)d_in[14];
    const float* W2     = (const float*)d_in[15];
    const float* b2     = (const float*)d_in[16];
    float* out = (float*)d_out;

    float *xn, *x2;
    __half *xnh, *qh, *kh, *vh, *kth, *aoh, *hnh, *h1h;
    __half *wqh, *wkh, *wvh, *woh, *w1h, *w2h;
    cudaGetSymbolAddress((void**)&xn,  g_xn);
    cudaGetSymbolAddress((void**)&xnh, g_xnh);
    cudaGetSymbolAddress((void**)&qh,  g_qh);
    cudaGetSymbolAddress((void**)&kh,  g_kh);
    cudaGetSymbolAddress((void**)&vh,  g_vh);
    cudaGetSymbolAddress((void**)&kth, g_kth);
    cudaGetSymbolAddress((void**)&aoh, g_aoh);
    cudaGetSymbolAddress((void**)&x2,  g_x2);
    cudaGetSymbolAddress((void**)&hnh, g_hnh);
    cudaGetSymbolAddress((void**)&h1h, g_h1h);
    cudaGetSymbolAddress((void**)&wqh, g_wqh);
    cudaGetSymbolAddress((void**)&wkh, g_wkh);
    cudaGetSymbolAddress((void**)&wvh, g_wvh);
    cudaGetSymbolAddress((void**)&woh, g_woh);
    cudaGetSymbolAddress((void**)&w1h, g_w1h);
    cudaGetSymbolAddress((void**)&w2h, g_w2h);

    // 0. fused weight fp16 pre-conversion
    wcvt_all<<<(4 * NQ4 + 2 * NF4) / 256, 256>>>(Wq, Wk, Wv, Wo, W1, W2,
                                                 wqh, wkh, wvh, woh, w1h, w2h);

    // 1. x_n = norm1(x): float (residual) + fp16 (GEMM A)
    norm_kernel<true><<<ROWS, 256>>>(x, alpha1, beta1, xn, xnh);

    // 2. fused Q/K/V projections (all fp16 out; Q x1/8)
    qkv_gemm5<<<dim3(24, ROWS / 128), 128>>>(xnh, wqh, wkh, wvh, bq, bk, bv,
                                             qh, kh, vh);

    // 3. K per-head transpose (fp16 -> fp16)
    htrans_h_kernel<<<dim3(SEQ / 64, BATCH * NH), 256>>>(kh, kth);

    // 4. fp16 flash attention (3-stage pipeline)
    cudaFuncSetAttribute(attn_h_kernel, cudaFuncAttributeMaxDynamicSharedMemorySize, ATTH_SMEM);
    attn_h_kernel<<<dim3(SEQ / 64, BATCH * NH), 128, ATTH_SMEM>>>(qh, kth, vh, aoh);

    // 5. x2 = x_n + ao@Wo + bo (fp32 out)
    tgemm5<false, true, 0><<<dim3(DM / 128, ROWS / 128), 128>>>(
        aoh, woh, bo, xn, x2, nullptr, DM, DM);

    // 6. h_n = norm2(x2): fp16 only
    norm_kernel<false><<<ROWS, 256>>>(x2, alpha2, beta2, nullptr, hnh);

    // 7. h1 = relu(h_n@W1 + b1), fp16 out
    tgemm5<true, false, 2><<<dim3(DFF / 128, ROWS / 128), 128>>>(
        hnh, w1h, b1, nullptr, nullptr, h1h, DFF, DM);

    // 8. out = x2 + h1@W2 + b2 (fp32)
    tgemm5<false, true, 0><<<dim3(DM / 128, ROWS / 128), 128>>>(
        h1h, w2h, b2, x2, out, nullptr, DM, DFF);
}